// round 14
// baseline (speedup 1.0000x reference)
#include <cuda_runtime.h>
#include <cuda_fp16.h>
#include <math.h>
#include <stdint.h>

// ---------------- problem constants ----------------
#define B_    2
#define S_    2048
#define DIM_  2048
#define H_    16
#define NOPE_ 128
#define ROPE_ 64
#define QKH_  192
#define KVR_  512
#define VD_   128
#define DQK_  576
#define BS_   (B_*S_)      // 4096
#define NQ_   (H_*QKH_)    // 3072

static const float SCALE_F = 0.07216878364870323f;   // 192^-0.5
typedef __half f16;

// ---------------- scratch ----------------
__device__ f16 g_x_h   [(size_t)BS_*DIM_];
__device__ f16 g_x_l   [(size_t)BS_*DIM_];
__device__ f16 g_wq_h  [(size_t)NQ_*DIM_];
__device__ f16 g_wq_l  [(size_t)NQ_*DIM_];
__device__ f16 g_wkva_h[(size_t)DQK_*DIM_];
__device__ f16 g_wkva_l[(size_t)DQK_*DIM_];
__device__ f16 g_wkvb_h[(size_t)4096*KVR_];
__device__ f16 g_wkvb_l[(size_t)4096*KVR_];
__device__ f16 g_wo_h  [(size_t)DIM_*H_*VD_];
__device__ f16 g_wo_l  [(size_t)DIM_*H_*VD_];
__device__ f16 g_qraw_h[(size_t)BS_*NQ_];
__device__ f16 g_qraw_l[(size_t)BS_*NQ_];
__device__ f16 g_kvr_h [(size_t)BS_*DQK_];
__device__ f16 g_kvr_l [(size_t)BS_*DQK_];
__device__ f16 g_kf_h  [(size_t)BS_*DQK_];
__device__ f16 g_kf_l  [(size_t)BS_*DQK_];
__device__ float g_scores[(size_t)B_*H_*S_*S_];
__device__ f16 g_attn_h[(size_t)B_*H_*S_*S_];
__device__ f16 g_qf_h  [(size_t)BS_*H_*DQK_];
__device__ f16 g_ol_h  [(size_t)BS_*H_*KVR_];
__device__ f16 g_ov_h  [(size_t)BS_*H_*VD_];
__device__ float g_cos [S_*(ROPE_/2)];
__device__ float g_sin [S_*(ROPE_/2)];

// ---------------- helpers ----------------
__device__ __forceinline__ uint32_t smem_u32(const void* p){
    uint32_t a;
    asm("{ .reg .u64 t; cvta.to.shared.u64 t, %1; cvt.u32.u64 %0, t; }" : "=r"(a) : "l"(p));
    return a;
}
__device__ __forceinline__ void split2h(float x, float y, uint32_t& h, uint32_t& l){
    __half2 hv = __floats2half2_rn(x, y);
    float2 hf = __half22float2(hv);
    __half2 lv = __floats2half2_rn(x - hf.x, y - hf.y);
    h = *reinterpret_cast<uint32_t*>(&hv);
    l = *reinterpret_cast<uint32_t*>(&lv);
}
__device__ __forceinline__ void split1h(float x, f16& h, f16& l){
    __half hv = __float2half_rn(x);
    h = hv;
    l = __float2half_rn(x - __half2float(hv));
}
__device__ __forceinline__ void ldm_x4(uint32_t* r, uint32_t addr){
    asm volatile("ldmatrix.sync.aligned.m8n8.x4.shared.b16 {%0,%1,%2,%3}, [%4];"
        : "=r"(r[0]),"=r"(r[1]),"=r"(r[2]),"=r"(r[3]) : "r"(addr));
}
__device__ __forceinline__ void ldm_x4t(uint32_t* r, uint32_t addr){
    asm volatile("ldmatrix.sync.aligned.m8n8.x4.trans.shared.b16 {%0,%1,%2,%3}, [%4];"
        : "=r"(r[0]),"=r"(r[1]),"=r"(r[2]),"=r"(r[3]) : "r"(addr));
}
__device__ __forceinline__ void mma_f16(float* c, const uint32_t* a, const uint32_t* b){
    asm volatile("mma.sync.aligned.m16n8k16.row.col.f32.f16.f16.f32 "
        "{%0,%1,%2,%3}, {%4,%5,%6,%7}, {%8,%9}, {%0,%1,%2,%3};"
        : "+f"(c[0]), "+f"(c[1]), "+f"(c[2]), "+f"(c[3])
        : "r"(a[0]), "r"(a[1]), "r"(a[2]), "r"(a[3]), "r"(b[0]), "r"(b[1]));
}
__device__ __forceinline__ void cp16(uint32_t s, const void* g, int sz){
    asm volatile("cp.async.ca.shared.global [%0], [%1], 16, %2;"
        :: "r"(s), "l"(g), "r"(sz) : "memory");
}
__device__ __forceinline__ void cp_commit(){ asm volatile("cp.async.commit_group;" ::: "memory"); }
template<int N> __device__ __forceinline__ void cp_wait(){ asm volatile("cp.async.wait_group %0;" :: "n"(N) : "memory"); }

// ---------------- GEMM: C = A * op(B), fp16 split, 128x128 tile, BK=32, single-sync ----
// NPROD 3: Ah*Bh + Ah*Bl + Al*Bh (warps 4m x 2n, 2-stage)
// NPROD 2: Ah*Bh + Ah*Bl         (warps 2m x 4n, 3-stage; Al never loaded/copied)
// EPI 0: fp32   EPI 1: f16 hi+lo   EPI 2: f16 hi only
#define A_PITCH_B 80
#define BN_PITCH_B 80
#define BK_PITCH_B 272
#define SMEM_DYN3 (2*40960)
#define SMEM_DYN2 (3*30720)

template<bool TRANS_B, bool CSKIP, bool CKLIM, int EPI, int NPROD>
__global__ void __launch_bounds__(256,2) tgemm_kernel(
    const f16* __restrict__ Ah, const f16* __restrict__ Al,
    const f16* __restrict__ Bh, const f16* __restrict__ Bl,
    float* __restrict__ Cf, f16* __restrict__ Ch, f16* __restrict__ Cl,
    int M, int N, int K, int lda, int ldb, int ldc,
    int divA, long long sA1, long long sA2,
    int divB, long long sB1, long long sB2,
    int divC, long long sC1, long long sC2)
{
    constexpr int BM = 128, BN = 128, BK = 32;
    constexpr int WMG = (NPROD == 2) ? 2 : 4;
    constexpr int WNG = 8 / WMG;
    constexpr int MT  = 8 / WMG;
    constexpr int NT  = 16 / WNG;
    constexpr int NPAIR = NT / 2;
    constexpr uint32_t B_HI  = (NPROD == 3) ? 20480u : 10240u;
    constexpr uint32_t BLO_D = TRANS_B ? 10240u : 8704u;
    constexpr uint32_t STAGE = (NPROD == 2) ? 30720u : 40960u;
    constexpr int NSTAGE = (NPROD == 2) ? 3 : 2;

    int by = blockIdx.y;
    if (CKLIM) by = gridDim.y - 1 - by;
    int m0 = by*BM, n0 = blockIdx.x*BN;
    if (CSKIP && n0 >= m0 + BM) return;
    int z = blockIdx.z;
    long long offA = (long long)(z/divA)*sA1 + (long long)(z%divA)*sA2;
    long long offB = (long long)(z/divB)*sB1 + (long long)(z%divB)*sB2;
    long long offC = (long long)(z/divC)*sC1 + (long long)(z%divC)*sC2;
    Ah += offA; Al += offA;
    Bh += offB; Bl += offB;
    if (EPI == 0) Cf += offC; else { Ch += offC; if (EPI == 1) Cl += offC; }
    int kEnd = CKLIM ? min(K, m0 + BM) : K;
    int nk = kEnd / BK;

    extern __shared__ __align__(128) char dyn_smem[];
    uint32_t sbase = smem_u32(dyn_smem);

    int tid  = threadIdx.x;
    int lane = tid & 31, wid = tid >> 5;
    int wm = wid % WMG, wn = wid / WMG;
    int mwarp = m0 + wm*(16*MT);
    int nwarp = n0 + wn*(8*NT);
    bool diag = CSKIP && (n0 == m0);

    int rowA = tid >> 1, segA = tid & 1;
    int rowB = tid >> 3, segB = tid & 7;

    auto copy_chunk = [&](int k0, uint32_t st){
        {
            const f16* g = Ah + (size_t)(m0+rowA)*lda + k0 + segA*16;
            uint32_t sd = st + (uint32_t)(rowA*A_PITCH_B + segA*32);
            cp16(sd, g, 16); cp16(sd+16, g+8, 16);
            if (NPROD == 3) {
                g = Al + (size_t)(m0+rowA)*lda + k0 + segA*16;
                sd += 10240;
                cp16(sd, g, 16); cp16(sd+16, g+8, 16);
            }
        }
        if (TRANS_B) {
            int ok = (n0+rowA) < N ? 16 : 0;
            size_t go = ok ? ((size_t)(n0+rowA)*ldb + k0 + segA*16) : 0;
            const f16* g = Bh + go;
            uint32_t sd = st + B_HI + (uint32_t)(rowA*BN_PITCH_B + segA*32);
            cp16(sd, g, ok); cp16(sd+16, g+8, ok);
            g = Bl + go;
            sd += BLO_D;
            cp16(sd, g, ok); cp16(sd+16, g+8, ok);
        } else {
            const f16* g = Bh + (size_t)(k0+rowB)*ldb + n0 + segB*16;
            uint32_t sd = st + B_HI + (uint32_t)(rowB*BK_PITCH_B + segB*32);
            cp16(sd, g, 16); cp16(sd+16, g+8, 16);
            g = Bl + (size_t)(k0+rowB)*ldb + n0 + segB*16;
            sd += BLO_D;
            cp16(sd, g, 16); cp16(sd+16, g+8, 16);
        }
    };

    float acc[MT][NT][4];
    #pragma unroll
    for (int i=0;i<MT;i++)
        #pragma unroll
        for (int j=0;j<NT;j++)
            #pragma unroll
            for (int q=0;q<4;q++) acc[i][j][q] = 0.f;

    uint32_t aOff   = (uint32_t)((wm*(16*MT) + (lane & 15))*A_PITCH_B + (lane >> 4)*16);
    uint32_t bOffT4 = (uint32_t)((wn*(8*NT) + (lane & 7) + ((lane >> 4)&1)*8)*BN_PITCH_B + ((lane >> 3)&1)*16);
    uint32_t bOffN4 = (uint32_t)((lane & 15)*BK_PITCH_B + wn*(8*NT)*2 + (lane >> 4)*16);

    // ---- prologue: fill pipeline
    copy_chunk(0, sbase);
    cp_commit();
    if (NSTAGE == 3 && nk > 1) {
        copy_chunk(BK, sbase + STAGE);
        cp_commit();
    }

    int sc = 0;                        // stage of current compute chunk
    int cstage = (NSTAGE == 3) ? 2 : 1;  // stage for next copy

    for (int kb = 0; kb < nk; kb++) {
        if (NSTAGE == 3) {
            if (kb + 1 < nk) cp_wait<1>(); else cp_wait<0>();
        } else {
            cp_wait<0>();
        }
        __syncthreads();
        int nxt = kb + (NSTAGE - 1);
        if (nxt < nk) {
            copy_chunk(nxt*BK, sbase + (uint32_t)cstage*STAGE);
            cp_commit();
            if (++cstage == NSTAGE) cstage = 0;
        } else if (NSTAGE == 2 && kb + 1 < nk) {
            // unreachable (NSTAGE==2 => nxt = kb+1)
        }

        uint32_t st = sbase + (uint32_t)sc*STAGE;
        if (++sc == NSTAGE) sc = 0;
        uint32_t sAh = st, sAl = st + 10240;
        uint32_t sBh = st + B_HI, sBl = sBh + BLO_D;

        #pragma unroll
        for (int ks = 0; ks < 2; ks++) {
            uint32_t ah[MT][4], al[MT][4];
            #pragma unroll
            for (int mt = 0; mt < MT; mt++) {
                ldm_x4(ah[mt], sAh + aOff + (uint32_t)(mt*16*A_PITCH_B + ks*32));
                if (NPROD == 3)
                    ldm_x4(al[mt], sAl + aOff + (uint32_t)(mt*16*A_PITCH_B + ks*32));
            }

            uint32_t bh[2][4], bl[2][4];
            if (TRANS_B) {
                ldm_x4 (bh[0], sBh + bOffT4 + (uint32_t)(ks*32));
                ldm_x4 (bl[0], sBl + bOffT4 + (uint32_t)(ks*32));
            } else {
                ldm_x4t(bh[0], sBh + bOffN4 + (uint32_t)(ks*16*BK_PITCH_B));
                ldm_x4t(bl[0], sBl + bOffN4 + (uint32_t)(ks*16*BK_PITCH_B));
            }
            #pragma unroll
            for (int p = 0; p < NPAIR; p++) {
                int cur = p & 1, nxt2 = cur ^ 1;
                if (p < NPAIR-1) {
                    if (TRANS_B) {
                        ldm_x4 (bh[nxt2], sBh + bOffT4 + (uint32_t)((p+1)*16*BN_PITCH_B + ks*32));
                        ldm_x4 (bl[nxt2], sBl + bOffT4 + (uint32_t)((p+1)*16*BN_PITCH_B + ks*32));
                    } else {
                        ldm_x4t(bh[nxt2], sBh + bOffN4 + (uint32_t)((p+1)*32 + ks*16*BK_PITCH_B));
                        ldm_x4t(bl[nxt2], sBl + bOffN4 + (uint32_t)((p+1)*32 + ks*16*BK_PITCH_B));
                    }
                }
                #pragma unroll
                for (int q = 0; q < 2; q++) {
                    int nt = p*2 + q;
                    if (diag && (nwarp + nt*8) > (mwarp + 16*MT - 1)) continue;  // warp-uniform
                    const uint32_t* BH = &bh[cur][q*2];
                    const uint32_t* BL = &bl[cur][q*2];
                    #pragma unroll
                    for (int mt = 0; mt < MT; mt++) mma_f16(acc[mt][nt], ah[mt], BH);
                    #pragma unroll
                    for (int mt = 0; mt < MT; mt++) mma_f16(acc[mt][nt], ah[mt], BL);
                    if (NPROD == 3) {
                        #pragma unroll
                        for (int mt = 0; mt < MT; mt++) mma_f16(acc[mt][nt], al[mt], BH);
                    }
                }
            }
        }
    }

    // ---- epilogue
    int rlo = lane >> 2;
    int cpair = (lane & 3)*2;
    #pragma unroll
    for (int mt = 0; mt < MT; mt++) {
        #pragma unroll
        for (int nt = 0; nt < NT; nt++) {
            int c = nwarp + nt*8 + cpair;
            if (c < N) {
                size_t r0 = (size_t)(mwarp + mt*16 + rlo);
                if (EPI == 0) {
                    *reinterpret_cast<float2*>(Cf + r0*ldc + c)     = make_float2(acc[mt][nt][0], acc[mt][nt][1]);
                    *reinterpret_cast<float2*>(Cf + (r0+8)*ldc + c) = make_float2(acc[mt][nt][2], acc[mt][nt][3]);
                } else {
                    uint32_t h, l;
                    split2h(acc[mt][nt][0], acc[mt][nt][1], h, l);
                    *reinterpret_cast<uint32_t*>(Ch + r0*ldc + c) = h;
                    if (EPI == 1) *reinterpret_cast<uint32_t*>(Cl + r0*ldc + c) = l;
                    split2h(acc[mt][nt][2], acc[mt][nt][3], h, l);
                    *reinterpret_cast<uint32_t*>(Ch + (r0+8)*ldc + c) = h;
                    if (EPI == 1) *reinterpret_cast<uint32_t*>(Cl + (r0+8)*ldc + c) = l;
                }
            }
        }
    }
}

// ---------------- single fused fp32 -> fp16 hi/lo split over all 5 tensors ----------------
__global__ void __launch_bounds__(256) split_all_kernel(
    const float* __restrict__ x, const float* __restrict__ wq,
    const float* __restrict__ wa, const float* __restrict__ wb,
    const float* __restrict__ wo)
{
    const long long c0 = (long long)BS_*DIM_/2;
    const long long c1 = c0 + (long long)NQ_*DIM_/2;
    const long long c2 = c1 + (long long)DQK_*DIM_/2;
    const long long c3 = c2 + (long long)4096*KVR_/2;
    const long long c4 = c3 + (long long)DIM_*H_*VD_/2;
    long long i = (long long)blockIdx.x*blockDim.x + threadIdx.x;
    if (i >= c4) return;
    const float* src; uint32_t *dh, *dl; long long j;
    if (i < c0)      { j = i;      src = x;  dh = (uint32_t*)g_x_h;    dl = (uint32_t*)g_x_l; }
    else if (i < c1) { j = i - c0; src = wq; dh = (uint32_t*)g_wq_h;   dl = (uint32_t*)g_wq_l; }
    else if (i < c2) { j = i - c1; src = wa; dh = (uint32_t*)g_wkva_h; dl = (uint32_t*)g_wkva_l; }
    else if (i < c3) { j = i - c2; src = wb; dh = (uint32_t*)g_wkvb_h; dl = (uint32_t*)g_wkvb_l; }
    else             { j = i - c3; src = wo; dh = (uint32_t*)g_wo_h;   dl = (uint32_t*)g_wo_l; }
    float2 v = reinterpret_cast<const float2*>(src)[j];
    uint32_t hh, ll;
    split2h(v.x, v.y, hh, ll);
    dh[j] = hh; dl[j] = ll;
}

// ---------------- RoPE tables ----------------
__global__ void rope_init_kernel() {
    int idx = blockIdx.x*blockDim.x + threadIdx.x;
    if (idx >= S_*(ROPE_/2)) return;
    int t = idx / (ROPE_/2);
    int i = idx % (ROPE_/2);
    double freq = pow(10000.0, -(double)(2*i)/(double)ROPE_);
    double ang  = (double)t * freq;
    g_cos[idx] = (float)cos(ang);
    g_sin[idx] = (float)sin(ang);
}

// ---------------- rmsnorm(kv_lat) + RoPE(k_pe, q_pe) -> split fp16 ----------------
__global__ void __launch_bounds__(256) prep_kernel(const float* __restrict__ kv_norm_w) {
    int bs  = blockIdx.x;
    int s   = bs % S_;
    int tid = threadIdx.x;
    const f16* kvh = g_kvr_h + (size_t)bs*DQK_;
    const f16* kvl = g_kvr_l + (size_t)bs*DQK_;
    f16* kfh = g_kf_h + (size_t)bs*DQK_;
    f16* kfl = g_kf_l + (size_t)bs*DQK_;

    __shared__ float red[256];
    float ss = 0.f;
    for (int j = tid; j < KVR_; j += 256) {
        float v = __half2float(kvh[j]) + __half2float(kvl[j]);
        ss += v*v;
    }
    red[tid] = ss; __syncthreads();
    #pragma unroll
    for (int o = 128; o > 0; o >>= 1) {
        if (tid < o) red[tid] += red[tid+o];
        __syncthreads();
    }
    float inv = 1.f / sqrtf(red[0] / (float)KVR_ + 1e-6f);

    for (int j = tid; j < KVR_; j += 256) {
        float v = __half2float(kvh[j]) + __half2float(kvl[j]);
        split1h(v * inv * kv_norm_w[j], kfh[j], kfl[j]);
    }

    for (int i = tid; i < ROPE_/2; i += 256) {
        float x0 = __half2float(kvh[KVR_+2*i]) + __half2float(kvl[KVR_+2*i]);
        float x1 = __half2float(kvh[KVR_+2*i+1]) + __half2float(kvl[KVR_+2*i+1]);
        float c = g_cos[s*(ROPE_/2)+i], sn = g_sin[s*(ROPE_/2)+i];
        split1h(x0*c - x1*sn, kfh[KVR_+2*i],   kfl[KVR_+2*i]);
        split1h(x0*sn + x1*c, kfh[KVR_+2*i+1], kfl[KVR_+2*i+1]);
    }

    const f16* qrh = g_qraw_h + (size_t)bs*NQ_;
    const f16* qrl = g_qraw_l + (size_t)bs*NQ_;
    f16* qfh = g_qf_h + (size_t)bs*H_*DQK_;
    for (int idx = tid; idx < H_*(ROPE_/2); idx += 256) {
        int h = idx >> 5, i = idx & 31;
        int src = h*QKH_ + NOPE_ + 2*i;
        float x0 = __half2float(qrh[src])   + __half2float(qrl[src]);
        float x1 = __half2float(qrh[src+1]) + __half2float(qrl[src+1]);
        float c = g_cos[s*(ROPE_/2)+i], sn = g_sin[s*(ROPE_/2)+i];
        int dst = h*DQK_ + KVR_ + 2*i;
        qfh[dst]   = __float2half_rn(x0*c - x1*sn);
        qfh[dst+1] = __float2half_rn(x0*sn + x1*c);
    }
}

// ---------------- lean causal softmax: fp32 scores -> fp16 hi attn ----------------
__global__ void __launch_bounds__(256) softmax_kernel() {
    int s = blockIdx.x;
    int z = blockIdx.y;
    size_t roff = ((size_t)z*S_ + s)*S_;
    const float* row = g_scores + roff;
    int n = s + 1;
    int pad = ((s >> 7) + 1) << 7;
    int tid = threadIdx.x;
    int base = tid*8;
    bool act = base < pad;

    float v[8];
    if (act) {
        *reinterpret_cast<float4*>(v)   = *reinterpret_cast<const float4*>(row + base);
        *reinterpret_cast<float4*>(v+4) = *reinterpret_cast<const float4*>(row + base + 4);
    }

    __shared__ float red[8];
    float mx = -3.4e38f;
    if (act) {
        #pragma unroll
        for (int e = 0; e < 8; e++) if (base + e < n) mx = fmaxf(mx, v[e]);
    }
    #pragma unroll
    for (int o = 16; o > 0; o >>= 1) mx = fmaxf(mx, __shfl_xor_sync(0xFFFFFFFFu, mx, o));
    if ((tid & 31) == 0) red[tid >> 5] = mx;
    __syncthreads();
    if (tid < 32) {
        float m = (tid < 8) ? red[tid] : -3.4e38f;
        #pragma unroll
        for (int o = 4; o > 0; o >>= 1) m = fmaxf(m, __shfl_xor_sync(0xFFFFFFFFu, m, o));
        if (tid == 0) red[0] = m;
    }
    __syncthreads();
    mx = red[0];
    __syncthreads();

    float e8[8];
    float sum = 0.f;
    #pragma unroll
    for (int e = 0; e < 8; e++) {
        float w = (act && base + e < n) ? expf((v[e] - mx) * SCALE_F) : 0.f;
        e8[e] = w; sum += w;
    }
    #pragma unroll
    for (int o = 16; o > 0; o >>= 1) sum += __shfl_xor_sync(0xFFFFFFFFu, sum, o);
    if ((tid & 31) == 0) red[tid >> 5] = sum;
    __syncthreads();
    if (tid < 32) {
        float m = (tid < 8) ? red[tid] : 0.f;
        #pragma unroll
        for (int o = 4; o > 0; o >>= 1) m += __shfl_xor_sync(0xFFFFFFFFu, m, o);
        if (tid == 0) red[0] = m;
    }
    __syncthreads();
    float inv = 1.f / red[0];

    if (act) {
        uint32_t* ah = reinterpret_cast<uint32_t*>(g_attn_h + roff + base);
        #pragma unroll
        for (int p = 0; p < 4; p++) {
            __half2 hv = __floats2half2_rn(e8[2*p]*inv, e8[2*p+1]*inv);
            ah[p] = *reinterpret_cast<uint32_t*>(&hv);
        }
    }
}

// ---------------- launch ----------------
extern "C" void kernel_launch(void* const* d_in, const int* in_sizes, int n_in,
                              void* d_out, int out_size) {
    const float* x      = (const float*)d_in[0];
    const float* wq     = (const float*)d_in[1];
    const float* wkv_a  = (const float*)d_in[2];
    const float* wkv_b  = (const float*)d_in[3];
    const float* wo     = (const float*)d_in[4];
    const float* kvw    = (const float*)d_in[5];
    float* out = (float*)d_out;

    f16 *xh,*xl,*wqh,*wql,*wah,*wal,*wbh,*wbl,*woh,*wol;
    f16 *qrh,*qrl,*kvh,*kvl,*kfh,*kfl,*qfh,*ath,*olh,*ovh;
    float *scores;
    cudaGetSymbolAddress((void**)&xh,  g_x_h);   cudaGetSymbolAddress((void**)&xl,  g_x_l);
    cudaGetSymbolAddress((void**)&wqh, g_wq_h);  cudaGetSymbolAddress((void**)&wql, g_wq_l);
    cudaGetSymbolAddress((void**)&wah, g_wkva_h);cudaGetSymbolAddress((void**)&wal, g_wkva_l);
    cudaGetSymbolAddress((void**)&wbh, g_wkvb_h);cudaGetSymbolAddress((void**)&wbl, g_wkvb_l);
    cudaGetSymbolAddress((void**)&woh, g_wo_h);  cudaGetSymbolAddress((void**)&wol, g_wo_l);
    cudaGetSymbolAddress((void**)&qrh, g_qraw_h);cudaGetSymbolAddress((void**)&qrl, g_qraw_l);
    cudaGetSymbolAddress((void**)&kvh, g_kvr_h); cudaGetSymbolAddress((void**)&kvl, g_kvr_l);
    cudaGetSymbolAddress((void**)&kfh, g_kf_h);  cudaGetSymbolAddress((void**)&kfl, g_kf_l);
    cudaGetSymbolAddress((void**)&qfh, g_qf_h);
    cudaGetSymbolAddress((void**)&ath, g_attn_h);
    cudaGetSymbolAddress((void**)&olh, g_ol_h);
    cudaGetSymbolAddress((void**)&ovh, g_ov_h);
    cudaGetSymbolAddress((void**)&scores, g_scores);

    cudaFuncSetAttribute(tgemm_kernel<true,false,false,1,3>,  cudaFuncAttributeMaxDynamicSharedMemorySize, SMEM_DYN3);
    cudaFuncSetAttribute(tgemm_kernel<true,false,false,1,2>,  cudaFuncAttributeMaxDynamicSharedMemorySize, SMEM_DYN2);
    cudaFuncSetAttribute(tgemm_kernel<false,false,false,2,2>, cudaFuncAttributeMaxDynamicSharedMemorySize, SMEM_DYN2);
    cudaFuncSetAttribute(tgemm_kernel<true,true,false,0,2>,   cudaFuncAttributeMaxDynamicSharedMemorySize, SMEM_DYN2);
    cudaFuncSetAttribute(tgemm_kernel<false,false,true,2,2>,  cudaFuncAttributeMaxDynamicSharedMemorySize, SMEM_DYN2);
    cudaFuncSetAttribute(tgemm_kernel<true,false,false,2,2>,  cudaFuncAttributeMaxDynamicSharedMemorySize, SMEM_DYN2);
    cudaFuncSetAttribute(tgemm_kernel<true,false,false,0,2>,  cudaFuncAttributeMaxDynamicSharedMemorySize, SMEM_DYN2);

    const long long tot_pairs = (long long)BS_*DIM_/2 + (long long)NQ_*DIM_/2
        + (long long)DQK_*DIM_/2 + (long long)4096*KVR_/2 + (long long)DIM_*H_*VD_/2;

    // 0) fused hi/lo split
    split_all_kernel<<<(int)((tot_pairs + 255)/256), 256>>>(x, wq, wkv_a, wkv_b, wo);

    // 1) RoPE tables
    rope_init_kernel<<<(S_*(ROPE_/2)+255)/256, 256>>>();

    // 2) kv_raw = x @ wkv_a^T  (3 products; feeds rmsnorm/k-cache)
    tgemm_kernel<true,false,false,1,3><<<dim3((DQK_+127)/128, BS_/128, 1), 256, SMEM_DYN3>>>(
        xh, xl, wah, wal, nullptr, kvh, kvl,
        BS_, DQK_, DIM_, DIM_, DIM_, DQK_,
        1,0,0, 1,0,0, 1,0,0);

    // 3) q_raw = x @ wq^T  (2 products)  <-- ncu captures 0-based launch index 3
    tgemm_kernel<true,false,false,1,2><<<dim3(NQ_/128, BS_/128, 1), 256, SMEM_DYN2>>>(
        xh, xl, wqh, wql, nullptr, qrh, qrl,
        BS_, NQ_, DIM_, DIM_, DIM_, NQ_,
        1,0,0, 1,0,0, 1,0,0);

    // 4) rmsnorm + rope
    prep_kernel<<<BS_, 256>>>(kvw);

    // 5) q_lat[h] = q_nope[:,h] @ wkv_b_h[h,:128,:]  (2 products, hi-only epilogue)
    tgemm_kernel<false,false,false,2,2><<<dim3(KVR_/128, BS_/128, H_), 256, SMEM_DYN2>>>(
        qrh, nullptr, wbh, wbl, nullptr, qfh, nullptr,
        BS_, KVR_, NOPE_, NQ_, KVR_, H_*DQK_,
        1, QKH_, 0,
        1, (long long)(NOPE_+VD_)*KVR_, 0,
        1, DQK_, 0);

    // 6) scores = qfull @ kfull^T  (2 products, causal tile skip + diag warp skip)
    tgemm_kernel<true,true,false,0,2><<<dim3(S_/128, S_/128, B_*H_), 256, SMEM_DYN2>>>(
        qfh, nullptr, kfh, kfl, scores, nullptr, nullptr,
        S_, S_, DQK_, H_*DQK_, DQK_, S_,
        H_, (long long)S_*H_*DQK_, DQK_,
        H_, (long long)S_*DQK_, 0,
        1, (long long)S_*S_, 0);

    // 7) lean softmax -> attn fp16 hi only
    softmax_kernel<<<dim3(S_, B_*H_), 256>>>();

    // 8) out_lat = attn @ kv_cache  (2 products, causal K-limit, hi-only out)
    tgemm_kernel<false,false,true,2,2><<<dim3(KVR_/128, S_/128, B_*H_), 256, SMEM_DYN2>>>(
        ath, nullptr, kfh, kfl, nullptr, olh, nullptr,
        S_, KVR_, S_, S_, DQK_, H_*KVR_,
        1, (long long)S_*S_, 0,
        H_, (long long)S_*DQK_, 0,
        H_, (long long)S_*H_*KVR_, KVR_);

    // 9) outv[:,h] = out_lat[:,h,:] @ wkv_b_h[h,128:,:]^T  (2 products, hi-only out)
    tgemm_kernel<true,false,false,2,2><<<dim3(VD_/128, BS_/128, H_), 256, SMEM_DYN2>>>(
        olh, nullptr, wbh + (size_t)NOPE_*KVR_, wbl + (size_t)NOPE_*KVR_, nullptr, ovh, nullptr,
        BS_, VD_, KVR_, H_*KVR_, KVR_, H_*VD_,
        1, KVR_, 0,
        1, (long long)(NOPE_+VD_)*KVR_, 0,
        1, VD_, 0);

    // 10) out = outv @ wo^T  (2 products)
    tgemm_kernel<true,false,false,0,2><<<dim3(DIM_/128, BS_/128, 1), 256, SMEM_DYN2>>>(
        ovh, nullptr, woh, wol, out, nullptr, nullptr,
        BS_, DIM_, H_*VD_, H_*VD_, H_*VD_, DIM_,
        1,0,0, 1,0,0, 1,0,0);
}

// round 15
// speedup vs baseline: 1.5056x; 1.5056x over previous
#include <cuda_runtime.h>
#include <cuda_fp16.h>
#include <math.h>
#include <stdint.h>

// ---------------- problem constants ----------------
#define B_    2
#define S_    2048
#define DIM_  2048
#define H_    16
#define NOPE_ 128
#define ROPE_ 64
#define QKH_  192
#define KVR_  512
#define VD_   128
#define DQK_  576
#define BS_   (B_*S_)      // 4096
#define NQ_   (H_*QKH_)    // 3072

static const float SCALE_F = 0.07216878364870323f;   // 192^-0.5
typedef __half f16;

// ---------------- scratch ----------------
__device__ f16 g_x_h   [(size_t)BS_*DIM_];
__device__ f16 g_x_l   [(size_t)BS_*DIM_];
__device__ f16 g_wq_h  [(size_t)NQ_*DIM_];
__device__ f16 g_wq_l  [(size_t)NQ_*DIM_];
__device__ f16 g_wkva_h[(size_t)DQK_*DIM_];
__device__ f16 g_wkva_l[(size_t)DQK_*DIM_];
__device__ f16 g_wkvb_h[(size_t)4096*KVR_];
__device__ f16 g_wkvb_l[(size_t)4096*KVR_];
__device__ f16 g_wo_h  [(size_t)DIM_*H_*VD_];
__device__ f16 g_wo_l  [(size_t)DIM_*H_*VD_];
__device__ f16 g_qraw_h[(size_t)BS_*NQ_];
__device__ f16 g_qraw_l[(size_t)BS_*NQ_];
__device__ f16 g_kvr_h [(size_t)BS_*DQK_];
__device__ f16 g_kvr_l [(size_t)BS_*DQK_];
__device__ f16 g_kf_h  [(size_t)BS_*DQK_];
__device__ f16 g_kf_l  [(size_t)BS_*DQK_];
__device__ float g_scores[(size_t)B_*H_*S_*S_];
__device__ f16 g_attn_h[(size_t)B_*H_*S_*S_];
__device__ f16 g_qf_h  [(size_t)BS_*H_*DQK_];
__device__ f16 g_ol_h  [(size_t)BS_*H_*KVR_];
__device__ f16 g_ov_h  [(size_t)BS_*H_*VD_];
__device__ float g_cos [S_*(ROPE_/2)];
__device__ float g_sin [S_*(ROPE_/2)];

// ---------------- helpers ----------------
__device__ __forceinline__ uint32_t smem_u32(const void* p){
    uint32_t a;
    asm("{ .reg .u64 t; cvta.to.shared.u64 t, %1; cvt.u32.u64 %0, t; }" : "=r"(a) : "l"(p));
    return a;
}
__device__ __forceinline__ void split2h(float x, float y, uint32_t& h, uint32_t& l){
    __half2 hv = __floats2half2_rn(x, y);
    float2 hf = __half22float2(hv);
    __half2 lv = __floats2half2_rn(x - hf.x, y - hf.y);
    h = *reinterpret_cast<uint32_t*>(&hv);
    l = *reinterpret_cast<uint32_t*>(&lv);
}
__device__ __forceinline__ void split1h(float x, f16& h, f16& l){
    __half hv = __float2half_rn(x);
    h = hv;
    l = __float2half_rn(x - __half2float(hv));
}
__device__ __forceinline__ void ldm_x4(uint32_t* r, uint32_t addr){
    asm volatile("ldmatrix.sync.aligned.m8n8.x4.shared.b16 {%0,%1,%2,%3}, [%4];"
        : "=r"(r[0]),"=r"(r[1]),"=r"(r[2]),"=r"(r[3]) : "r"(addr));
}
__device__ __forceinline__ void ldm_x4t(uint32_t* r, uint32_t addr){
    asm volatile("ldmatrix.sync.aligned.m8n8.x4.trans.shared.b16 {%0,%1,%2,%3}, [%4];"
        : "=r"(r[0]),"=r"(r[1]),"=r"(r[2]),"=r"(r[3]) : "r"(addr));
}
__device__ __forceinline__ void mma_f16(float* c, const uint32_t* a, const uint32_t* b){
    asm volatile("mma.sync.aligned.m16n8k16.row.col.f32.f16.f16.f32 "
        "{%0,%1,%2,%3}, {%4,%5,%6,%7}, {%8,%9}, {%0,%1,%2,%3};"
        : "+f"(c[0]), "+f"(c[1]), "+f"(c[2]), "+f"(c[3])
        : "r"(a[0]), "r"(a[1]), "r"(a[2]), "r"(a[3]), "r"(b[0]), "r"(b[1]));
}
__device__ __forceinline__ void cp16(uint32_t s, const void* g, int sz){
    asm volatile("cp.async.cg.shared.global [%0], [%1], 16, %2;"
        :: "r"(s), "l"(g), "r"(sz) : "memory");
}
__device__ __forceinline__ void cp_commit(){ asm volatile("cp.async.commit_group;" ::: "memory"); }
template<int N> __device__ __forceinline__ void cp_wait(){ asm volatile("cp.async.wait_group %0;" :: "n"(N) : "memory"); }

// ---------------- GEMM: C = A * op(B), fp16 split, 128x128 tile, BK=32, single-sync ----
// NPROD 3: Ah*Bh + Ah*Bl + Al*Bh (warps 4m x 2n)
// NPROD 2: Ah*Bh + Ah*Bl         (warps 2m x 4n; Al never loaded/copied)
// EPI 0: fp32   EPI 1: f16 hi+lo   EPI 2: f16 hi only
#define A_PITCH_B 80
#define BN_PITCH_B 80
#define BK_PITCH_B 272
#define STAGE_BYTES 40960
#define SMEM_DYN (2*STAGE_BYTES)

template<bool TRANS_B, bool CSKIP, bool CKLIM, int EPI, int NPROD>
__global__ void __launch_bounds__(256,2) tgemm_kernel(
    const f16* __restrict__ Ah, const f16* __restrict__ Al,
    const f16* __restrict__ Bh, const f16* __restrict__ Bl,
    float* __restrict__ Cf, f16* __restrict__ Ch, f16* __restrict__ Cl,
    int M, int N, int K, int lda, int ldb, int ldc,
    int divA, long long sA1, long long sA2,
    int divB, long long sB1, long long sB2,
    int divC, long long sC1, long long sC2)
{
    constexpr int BM = 128, BN = 128, BK = 32;
    constexpr int WMG = (NPROD == 2) ? 2 : 4;
    constexpr int WNG = 8 / WMG;
    constexpr int MT  = 8 / WMG;
    constexpr int NT  = 16 / WNG;
    constexpr int NPAIR = NT / 2;

    int by = blockIdx.y;
    if (CKLIM) by = gridDim.y - 1 - by;
    int m0 = by*BM, n0 = blockIdx.x*BN;
    if (CSKIP && n0 >= m0 + BM) return;
    int z = blockIdx.z;
    long long offA = (long long)(z/divA)*sA1 + (long long)(z%divA)*sA2;
    long long offB = (long long)(z/divB)*sB1 + (long long)(z%divB)*sB2;
    long long offC = (long long)(z/divC)*sC1 + (long long)(z%divC)*sC2;
    Ah += offA; Al += offA;
    Bh += offB; Bl += offB;
    if (EPI == 0) Cf += offC; else { Ch += offC; if (EPI == 1) Cl += offC; }
    int kEnd = CKLIM ? min(K, m0 + BM) : K;
    int nk = kEnd / BK;

    extern __shared__ __align__(128) char dyn_smem[];
    uint32_t sbase = smem_u32(dyn_smem);
    const uint32_t B_HI_OFF = 20480u;
    const uint32_t BLO_D = TRANS_B ? 10240u : 8704u;

    int tid  = threadIdx.x;
    int lane = tid & 31, wid = tid >> 5;
    int wm = wid % WMG, wn = wid / WMG;
    int mwarp = m0 + wm*(16*MT);
    int nwarp = n0 + wn*(8*NT);
    bool diag = CSKIP && (n0 == m0);

    int rowA = tid >> 1, segA = tid & 1;
    int rowB = tid >> 3, segB = tid & 7;

    auto copy_chunk = [&](int k0, uint32_t st){
        {
            const f16* g = Ah + (size_t)(m0+rowA)*lda + k0 + segA*16;
            uint32_t sd = st + (uint32_t)(rowA*A_PITCH_B + segA*32);
            cp16(sd, g, 16); cp16(sd+16, g+8, 16);
            if (NPROD == 3) {
                g = Al + (size_t)(m0+rowA)*lda + k0 + segA*16;
                sd += 10240;
                cp16(sd, g, 16); cp16(sd+16, g+8, 16);
            }
        }
        if (TRANS_B) {
            int ok = (n0+rowA) < N ? 16 : 0;
            size_t go = ok ? ((size_t)(n0+rowA)*ldb + k0 + segA*16) : 0;
            const f16* g = Bh + go;
            uint32_t sd = st + B_HI_OFF + (uint32_t)(rowA*BN_PITCH_B + segA*32);
            cp16(sd, g, ok); cp16(sd+16, g+8, ok);
            g = Bl + go;
            sd += BLO_D;
            cp16(sd, g, ok); cp16(sd+16, g+8, ok);
        } else {
            const f16* g = Bh + (size_t)(k0+rowB)*ldb + n0 + segB*16;
            uint32_t sd = st + B_HI_OFF + (uint32_t)(rowB*BK_PITCH_B + segB*32);
            cp16(sd, g, 16); cp16(sd+16, g+8, 16);
            g = Bl + (size_t)(k0+rowB)*ldb + n0 + segB*16;
            sd += BLO_D;
            cp16(sd, g, 16); cp16(sd+16, g+8, 16);
        }
    };

    float acc[MT][NT][4];
    #pragma unroll
    for (int i=0;i<MT;i++)
        #pragma unroll
        for (int j=0;j<NT;j++)
            #pragma unroll
            for (int q=0;q<4;q++) acc[i][j][q] = 0.f;

    uint32_t aOff   = (uint32_t)((wm*(16*MT) + (lane & 15))*A_PITCH_B + (lane >> 4)*16);
    uint32_t bOffT4 = (uint32_t)((wn*(8*NT) + (lane & 7) + ((lane >> 4)&1)*8)*BN_PITCH_B + ((lane >> 3)&1)*16);
    uint32_t bOffN4 = (uint32_t)((lane & 15)*BK_PITCH_B + wn*(8*NT)*2 + (lane >> 4)*16);

    copy_chunk(0, sbase);
    cp_commit();

    for (int kb = 0; kb < nk; kb++) {
        cp_wait<0>();
        __syncthreads();
        if (kb + 1 < nk) {
            copy_chunk((kb+1)*BK, sbase + ((kb+1)&1)*STAGE_BYTES);
            cp_commit();
        }

        uint32_t st = sbase + (kb&1)*STAGE_BYTES;
        uint32_t sAh = st, sAl = st + 10240;
        uint32_t sBh = st + B_HI_OFF, sBl = sBh + BLO_D;

        #pragma unroll
        for (int ks = 0; ks < 2; ks++) {
            uint32_t ah[MT][4], al[MT][4];
            #pragma unroll
            for (int mt = 0; mt < MT; mt++) {
                ldm_x4(ah[mt], sAh + aOff + (uint32_t)(mt*16*A_PITCH_B + ks*32));
                if (NPROD == 3)
                    ldm_x4(al[mt], sAl + aOff + (uint32_t)(mt*16*A_PITCH_B + ks*32));
            }

            uint32_t bh[2][4], bl[2][4];
            if (TRANS_B) {
                ldm_x4 (bh[0], sBh + bOffT4 + (uint32_t)(ks*32));
                ldm_x4 (bl[0], sBl + bOffT4 + (uint32_t)(ks*32));
            } else {
                ldm_x4t(bh[0], sBh + bOffN4 + (uint32_t)(ks*16*BK_PITCH_B));
                ldm_x4t(bl[0], sBl + bOffN4 + (uint32_t)(ks*16*BK_PITCH_B));
            }
            #pragma unroll
            for (int p = 0; p < NPAIR; p++) {
                int cur = p & 1, nxt = cur ^ 1;
                if (p < NPAIR-1) {
                    if (TRANS_B) {
                        ldm_x4 (bh[nxt], sBh + bOffT4 + (uint32_t)((p+1)*16*BN_PITCH_B + ks*32));
                        ldm_x4 (bl[nxt], sBl + bOffT4 + (uint32_t)((p+1)*16*BN_PITCH_B + ks*32));
                    } else {
                        ldm_x4t(bh[nxt], sBh + bOffN4 + (uint32_t)((p+1)*32 + ks*16*BK_PITCH_B));
                        ldm_x4t(bl[nxt], sBl + bOffN4 + (uint32_t)((p+1)*32 + ks*16*BK_PITCH_B));
                    }
                }
                #pragma unroll
                for (int q = 0; q < 2; q++) {
                    int nt = p*2 + q;
                    if (diag && (nwarp + nt*8) > (mwarp + 16*MT - 1)) continue;  // warp-uniform
                    const uint32_t* BH = &bh[cur][q*2];
                    const uint32_t* BL = &bl[cur][q*2];
                    #pragma unroll
                    for (int mt = 0; mt < MT; mt++) mma_f16(acc[mt][nt], ah[mt], BH);
                    #pragma unroll
                    for (int mt = 0; mt < MT; mt++) mma_f16(acc[mt][nt], ah[mt], BL);
                    if (NPROD == 3) {
                        #pragma unroll
                        for (int mt = 0; mt < MT; mt++) mma_f16(acc[mt][nt], al[mt], BH);
                    }
                }
            }
        }
    }

    // ---- epilogue
    int rlo = lane >> 2;
    int cpair = (lane & 3)*2;
    #pragma unroll
    for (int mt = 0; mt < MT; mt++) {
        #pragma unroll
        for (int nt = 0; nt < NT; nt++) {
            int c = nwarp + nt*8 + cpair;
            if (c < N) {
                size_t r0 = (size_t)(mwarp + mt*16 + rlo);
                if (EPI == 0) {
                    *reinterpret_cast<float2*>(Cf + r0*ldc + c)     = make_float2(acc[mt][nt][0], acc[mt][nt][1]);
                    *reinterpret_cast<float2*>(Cf + (r0+8)*ldc + c) = make_float2(acc[mt][nt][2], acc[mt][nt][3]);
                } else {
                    uint32_t h, l;
                    split2h(acc[mt][nt][0], acc[mt][nt][1], h, l);
                    *reinterpret_cast<uint32_t*>(Ch + r0*ldc + c) = h;
                    if (EPI == 1) *reinterpret_cast<uint32_t*>(Cl + r0*ldc + c) = l;
                    split2h(acc[mt][nt][2], acc[mt][nt][3], h, l);
                    *reinterpret_cast<uint32_t*>(Ch + (r0+8)*ldc + c) = h;
                    if (EPI == 1) *reinterpret_cast<uint32_t*>(Cl + (r0+8)*ldc + c) = l;
                }
            }
        }
    }
}

// ---------------- single fused fp32 -> fp16 hi/lo split over all 5 tensors ----------------
__global__ void __launch_bounds__(256) split_all_kernel(
    const float* __restrict__ x, const float* __restrict__ wq,
    const float* __restrict__ wa, const float* __restrict__ wb,
    const float* __restrict__ wo)
{
    const long long c0 = (long long)BS_*DIM_/2;
    const long long c1 = c0 + (long long)NQ_*DIM_/2;
    const long long c2 = c1 + (long long)DQK_*DIM_/2;
    const long long c3 = c2 + (long long)4096*KVR_/2;
    const long long c4 = c3 + (long long)DIM_*H_*VD_/2;
    long long i = (long long)blockIdx.x*blockDim.x + threadIdx.x;
    if (i >= c4) return;
    const float* src; uint32_t *dh, *dl; long long j;
    if (i < c0)      { j = i;      src = x;  dh = (uint32_t*)g_x_h;    dl = (uint32_t*)g_x_l; }
    else if (i < c1) { j = i - c0; src = wq; dh = (uint32_t*)g_wq_h;   dl = (uint32_t*)g_wq_l; }
    else if (i < c2) { j = i - c1; src = wa; dh = (uint32_t*)g_wkva_h; dl = (uint32_t*)g_wkva_l; }
    else if (i < c3) { j = i - c2; src = wb; dh = (uint32_t*)g_wkvb_h; dl = (uint32_t*)g_wkvb_l; }
    else             { j = i - c3; src = wo; dh = (uint32_t*)g_wo_h;   dl = (uint32_t*)g_wo_l; }
    float2 v = reinterpret_cast<const float2*>(src)[j];
    uint32_t hh, ll;
    split2h(v.x, v.y, hh, ll);
    dh[j] = hh; dl[j] = ll;
}

// ---------------- RoPE tables ----------------
__global__ void rope_init_kernel() {
    int idx = blockIdx.x*blockDim.x + threadIdx.x;
    if (idx >= S_*(ROPE_/2)) return;
    int t = idx / (ROPE_/2);
    int i = idx % (ROPE_/2);
    double freq = pow(10000.0, -(double)(2*i)/(double)ROPE_);
    double ang  = (double)t * freq;
    g_cos[idx] = (float)cos(ang);
    g_sin[idx] = (float)sin(ang);
}

// ---------------- rmsnorm(kv_lat) + RoPE(k_pe, q_pe) -> split fp16 ----------------
__global__ void __launch_bounds__(256) prep_kernel(const float* __restrict__ kv_norm_w) {
    int bs  = blockIdx.x;
    int s   = bs % S_;
    int tid = threadIdx.x;
    const f16* kvh = g_kvr_h + (size_t)bs*DQK_;
    const f16* kvl = g_kvr_l + (size_t)bs*DQK_;
    f16* kfh = g_kf_h + (size_t)bs*DQK_;
    f16* kfl = g_kf_l + (size_t)bs*DQK_;

    __shared__ float red[256];
    float ss = 0.f;
    for (int j = tid; j < KVR_; j += 256) {
        float v = __half2float(kvh[j]) + __half2float(kvl[j]);
        ss += v*v;
    }
    red[tid] = ss; __syncthreads();
    #pragma unroll
    for (int o = 128; o > 0; o >>= 1) {
        if (tid < o) red[tid] += red[tid+o];
        __syncthreads();
    }
    float inv = 1.f / sqrtf(red[0] / (float)KVR_ + 1e-6f);

    for (int j = tid; j < KVR_; j += 256) {
        float v = __half2float(kvh[j]) + __half2float(kvl[j]);
        split1h(v * inv * kv_norm_w[j], kfh[j], kfl[j]);
    }

    for (int i = tid; i < ROPE_/2; i += 256) {
        float x0 = __half2float(kvh[KVR_+2*i]) + __half2float(kvl[KVR_+2*i]);
        float x1 = __half2float(kvh[KVR_+2*i+1]) + __half2float(kvl[KVR_+2*i+1]);
        float c = g_cos[s*(ROPE_/2)+i], sn = g_sin[s*(ROPE_/2)+i];
        split1h(x0*c - x1*sn, kfh[KVR_+2*i],   kfl[KVR_+2*i]);
        split1h(x0*sn + x1*c, kfh[KVR_+2*i+1], kfl[KVR_+2*i+1]);
    }

    const f16* qrh = g_qraw_h + (size_t)bs*NQ_;
    const f16* qrl = g_qraw_l + (size_t)bs*NQ_;
    f16* qfh = g_qf_h + (size_t)bs*H_*DQK_;
    for (int idx = tid; idx < H_*(ROPE_/2); idx += 256) {
        int h = idx >> 5, i = idx & 31;
        int src = h*QKH_ + NOPE_ + 2*i;
        float x0 = __half2float(qrh[src])   + __half2float(qrl[src]);
        float x1 = __half2float(qrh[src+1]) + __half2float(qrl[src+1]);
        float c = g_cos[s*(ROPE_/2)+i], sn = g_sin[s*(ROPE_/2)+i];
        int dst = h*DQK_ + KVR_ + 2*i;
        qfh[dst]   = __float2half_rn(x0*c - x1*sn);
        qfh[dst+1] = __float2half_rn(x0*sn + x1*c);
    }
}

// ---------------- lean causal softmax: fp32 scores -> fp16 hi attn ----------------
__global__ void __launch_bounds__(256) softmax_kernel() {
    int s = blockIdx.x;
    int z = blockIdx.y;
    size_t roff = ((size_t)z*S_ + s)*S_;
    const float* row = g_scores + roff;
    int n = s + 1;
    int pad = ((s >> 7) + 1) << 7;
    int tid = threadIdx.x;
    int base = tid*8;
    bool act = base < pad;

    float v[8];
    if (act) {
        *reinterpret_cast<float4*>(v)   = *reinterpret_cast<const float4*>(row + base);
        *reinterpret_cast<float4*>(v+4) = *reinterpret_cast<const float4*>(row + base + 4);
    }

    __shared__ float red[8];
    float mx = -3.4e38f;
    if (act) {
        #pragma unroll
        for (int e = 0; e < 8; e++) if (base + e < n) mx = fmaxf(mx, v[e]);
    }
    #pragma unroll
    for (int o = 16; o > 0; o >>= 1) mx = fmaxf(mx, __shfl_xor_sync(0xFFFFFFFFu, mx, o));
    if ((tid & 31) == 0) red[tid >> 5] = mx;
    __syncthreads();
    if (tid < 32) {
        float m = (tid < 8) ? red[tid] : -3.4e38f;
        #pragma unroll
        for (int o = 4; o > 0; o >>= 1) m = fmaxf(m, __shfl_xor_sync(0xFFFFFFFFu, m, o));
        if (tid == 0) red[0] = m;
    }
    __syncthreads();
    mx = red[0];
    __syncthreads();

    float e8[8];
    float sum = 0.f;
    #pragma unroll
    for (int e = 0; e < 8; e++) {
        float w = (act && base + e < n) ? expf((v[e] - mx) * SCALE_F) : 0.f;
        e8[e] = w; sum += w;
    }
    #pragma unroll
    for (int o = 16; o > 0; o >>= 1) sum += __shfl_xor_sync(0xFFFFFFFFu, sum, o);
    if ((tid & 31) == 0) red[tid >> 5] = sum;
    __syncthreads();
    if (tid < 32) {
        float m = (tid < 8) ? red[tid] : 0.f;
        #pragma unroll
        for (int o = 4; o > 0; o >>= 1) m += __shfl_xor_sync(0xFFFFFFFFu, m, o);
        if (tid == 0) red[0] = m;
    }
    __syncthreads();
    float inv = 1.f / red[0];

    if (act) {
        uint32_t* ah = reinterpret_cast<uint32_t*>(g_attn_h + roff + base);
        #pragma unroll
        for (int p = 0; p < 4; p++) {
            __half2 hv = __floats2half2_rn(e8[2*p]*inv, e8[2*p+1]*inv);
            ah[p] = *reinterpret_cast<uint32_t*>(&hv);
        }
    }
}

// ---------------- launch ----------------
extern "C" void kernel_launch(void* const* d_in, const int* in_sizes, int n_in,
                              void* d_out, int out_size) {
    const float* x      = (const float*)d_in[0];
    const float* wq     = (const float*)d_in[1];
    const float* wkv_a  = (const float*)d_in[2];
    const float* wkv_b  = (const float*)d_in[3];
    const float* wo     = (const float*)d_in[4];
    const float* kvw    = (const float*)d_in[5];
    float* out = (float*)d_out;

    f16 *xh,*xl,*wqh,*wql,*wah,*wal,*wbh,*wbl,*woh,*wol;
    f16 *qrh,*qrl,*kvh,*kvl,*kfh,*kfl,*qfh,*ath,*olh,*ovh;
    float *scores;
    cudaGetSymbolAddress((void**)&xh,  g_x_h);   cudaGetSymbolAddress((void**)&xl,  g_x_l);
    cudaGetSymbolAddress((void**)&wqh, g_wq_h);  cudaGetSymbolAddress((void**)&wql, g_wq_l);
    cudaGetSymbolAddress((void**)&wah, g_wkva_h);cudaGetSymbolAddress((void**)&wal, g_wkva_l);
    cudaGetSymbolAddress((void**)&wbh, g_wkvb_h);cudaGetSymbolAddress((void**)&wbl, g_wkvb_l);
    cudaGetSymbolAddress((void**)&woh, g_wo_h);  cudaGetSymbolAddress((void**)&wol, g_wo_l);
    cudaGetSymbolAddress((void**)&qrh, g_qraw_h);cudaGetSymbolAddress((void**)&qrl, g_qraw_l);
    cudaGetSymbolAddress((void**)&kvh, g_kvr_h); cudaGetSymbolAddress((void**)&kvl, g_kvr_l);
    cudaGetSymbolAddress((void**)&kfh, g_kf_h);  cudaGetSymbolAddress((void**)&kfl, g_kf_l);
    cudaGetSymbolAddress((void**)&qfh, g_qf_h);
    cudaGetSymbolAddress((void**)&ath, g_attn_h);
    cudaGetSymbolAddress((void**)&olh, g_ol_h);
    cudaGetSymbolAddress((void**)&ovh, g_ov_h);
    cudaGetSymbolAddress((void**)&scores, g_scores);

    cudaFuncSetAttribute(tgemm_kernel<true,false,false,1,3>,  cudaFuncAttributeMaxDynamicSharedMemorySize, SMEM_DYN);
    cudaFuncSetAttribute(tgemm_kernel<true,false,false,1,2>,  cudaFuncAttributeMaxDynamicSharedMemorySize, SMEM_DYN);
    cudaFuncSetAttribute(tgemm_kernel<false,false,false,2,2>, cudaFuncAttributeMaxDynamicSharedMemorySize, SMEM_DYN);
    cudaFuncSetAttribute(tgemm_kernel<true,true,false,0,2>,   cudaFuncAttributeMaxDynamicSharedMemorySize, SMEM_DYN);
    cudaFuncSetAttribute(tgemm_kernel<false,false,true,2,2>,  cudaFuncAttributeMaxDynamicSharedMemorySize, SMEM_DYN);
    cudaFuncSetAttribute(tgemm_kernel<true,false,false,2,2>,  cudaFuncAttributeMaxDynamicSharedMemorySize, SMEM_DYN);
    cudaFuncSetAttribute(tgemm_kernel<true,false,false,0,2>,  cudaFuncAttributeMaxDynamicSharedMemorySize, SMEM_DYN);

    const long long tot_pairs = (long long)BS_*DIM_/2 + (long long)NQ_*DIM_/2
        + (long long)DQK_*DIM_/2 + (long long)4096*KVR_/2 + (long long)DIM_*H_*VD_/2;

    // 0) fused hi/lo split
    split_all_kernel<<<(int)((tot_pairs + 255)/256), 256>>>(x, wq, wkv_a, wkv_b, wo);

    // 1) RoPE tables
    rope_init_kernel<<<(S_*(ROPE_/2)+255)/256, 256>>>();

    // 2) kv_raw = x @ wkv_a^T  (3 products; feeds rmsnorm/k-cache)
    tgemm_kernel<true,false,false,1,3><<<dim3((DQK_+127)/128, BS_/128, 1), 256, SMEM_DYN>>>(
        xh, xl, wah, wal, nullptr, kvh, kvl,
        BS_, DQK_, DIM_, DIM_, DIM_, DQK_,
        1,0,0, 1,0,0, 1,0,0);

    // 3) q_raw = x @ wq^T  (2 products)  <-- ncu captures 0-based launch index 3
    tgemm_kernel<true,false,false,1,2><<<dim3(NQ_/128, BS_/128, 1), 256, SMEM_DYN>>>(
        xh, xl, wqh, wql, nullptr, qrh, qrl,
        BS_, NQ_, DIM_, DIM_, DIM_, NQ_,
        1,0,0, 1,0,0, 1,0,0);

    // 4) rmsnorm + rope
    prep_kernel<<<BS_, 256>>>(kvw);

    // 5) q_lat[h] = q_nope[:,h] @ wkv_b_h[h,:128,:]  (2 products, hi-only epilogue)
    tgemm_kernel<false,false,false,2,2><<<dim3(KVR_/128, BS_/128, H_), 256, SMEM_DYN>>>(
        qrh, nullptr, wbh, wbl, nullptr, qfh, nullptr,
        BS_, KVR_, NOPE_, NQ_, KVR_, H_*DQK_,
        1, QKH_, 0,
        1, (long long)(NOPE_+VD_)*KVR_, 0,
        1, DQK_, 0);

    // 6) scores = qfull @ kfull^T  (2 products, causal tile skip + diag warp skip)
    tgemm_kernel<true,true,false,0,2><<<dim3(S_/128, S_/128, B_*H_), 256, SMEM_DYN>>>(
        qfh, nullptr, kfh, kfl, scores, nullptr, nullptr,
        S_, S_, DQK_, H_*DQK_, DQK_, S_,
        H_, (long long)S_*H_*DQK_, DQK_,
        H_, (long long)S_*DQK_, 0,
        1, (long long)S_*S_, 0);

    // 7) lean softmax -> attn fp16 hi only
    softmax_kernel<<<dim3(S_, B_*H_), 256>>>();

    // 8) out_lat = attn @ kv_cache  (2 products, causal K-limit, hi-only out)
    tgemm_kernel<false,false,true,2,2><<<dim3(KVR_/128, S_/128, B_*H_), 256, SMEM_DYN>>>(
        ath, nullptr, kfh, kfl, nullptr, olh, nullptr,
        S_, KVR_, S_, S_, DQK_, H_*KVR_,
        1, (long long)S_*S_, 0,
        H_, (long long)S_*DQK_, 0,
        H_, (long long)S_*H_*KVR_, KVR_);

    // 9) outv[:,h] = out_lat[:,h,:] @ wkv_b_h[h,128:,:]^T  (2 products, hi-only out)
    tgemm_kernel<true,false,false,2,2><<<dim3(VD_/128, BS_/128, H_), 256, SMEM_DYN>>>(
        olh, nullptr, wbh + (size_t)NOPE_*KVR_, wbl + (size_t)NOPE_*KVR_, nullptr, ovh, nullptr,
        BS_, VD_, KVR_, H_*KVR_, KVR_, H_*VD_,
        1, KVR_, 0,
        1, (long long)(NOPE_+VD_)*KVR_, 0,
        1, VD_, 0);

    // 10) out = outv @ wo^T  (2 products)
    tgemm_kernel<true,false,false,0,2><<<dim3(DIM_/128, BS_/128, 1), 256, SMEM_DYN>>>(
        ovh, nullptr, woh, wol, out, nullptr, nullptr,
        BS_, DIM_, H_*VD_, H_*VD_, H_*VD_, DIM_,
        1,0,0, 1,0,0, 1,0,0);
}

// round 16
// speedup vs baseline: 1.7914x; 1.1898x over previous
#include <cuda_runtime.h>
#include <cuda_fp16.h>
#include <math.h>
#include <stdint.h>

// ---------------- problem constants ----------------
#define B_    2
#define S_    2048
#define DIM_  2048
#define H_    16
#define NOPE_ 128
#define ROPE_ 64
#define QKH_  192
#define KVR_  512
#define VD_   128
#define DQK_  576
#define BS_   (B_*S_)      // 4096
#define NQ_   (H_*QKH_)    // 3072

static const float SCALE_F = 0.07216878364870323f;   // 192^-0.5
typedef __half f16;

// ---------------- scratch ----------------
__device__ f16 g_x_h   [(size_t)BS_*DIM_];
__device__ f16 g_x_l   [(size_t)BS_*DIM_];
__device__ f16 g_wq_h  [(size_t)NQ_*DIM_];
__device__ f16 g_wq_l  [(size_t)NQ_*DIM_];
__device__ f16 g_wkva_h[(size_t)DQK_*DIM_];
__device__ f16 g_wkva_l[(size_t)DQK_*DIM_];
__device__ f16 g_wkvb_h[(size_t)4096*KVR_];
__device__ f16 g_wkvb_l[(size_t)4096*KVR_];
__device__ f16 g_wo_h  [(size_t)DIM_*H_*VD_];
__device__ f16 g_wo_l  [(size_t)DIM_*H_*VD_];
__device__ f16 g_qraw_h[(size_t)BS_*NQ_];
__device__ f16 g_qraw_l[(size_t)BS_*NQ_];
__device__ f16 g_kvr_h [(size_t)BS_*DQK_];
__device__ f16 g_kvr_l [(size_t)BS_*DQK_];
__device__ f16 g_kf_h  [(size_t)BS_*DQK_];
__device__ f16 g_kf_l  [(size_t)BS_*DQK_];
__device__ float g_scores[(size_t)B_*H_*S_*S_];
__device__ f16 g_attn_h[(size_t)B_*H_*S_*S_];
__device__ f16 g_qf_h  [(size_t)BS_*H_*DQK_];
__device__ f16 g_ol_h  [(size_t)BS_*H_*KVR_];
__device__ f16 g_ov_h  [(size_t)BS_*H_*VD_];
__device__ float g_cos [S_*(ROPE_/2)];
__device__ float g_sin [S_*(ROPE_/2)];

// ---------------- helpers ----------------
__device__ __forceinline__ uint32_t smem_u32(const void* p){
    uint32_t a;
    asm("{ .reg .u64 t; cvta.to.shared.u64 t, %1; cvt.u32.u64 %0, t; }" : "=r"(a) : "l"(p));
    return a;
}
__device__ __forceinline__ void split2h(float x, float y, uint32_t& h, uint32_t& l){
    __half2 hv = __floats2half2_rn(x, y);
    float2 hf = __half22float2(hv);
    __half2 lv = __floats2half2_rn(x - hf.x, y - hf.y);
    h = *reinterpret_cast<uint32_t*>(&hv);
    l = *reinterpret_cast<uint32_t*>(&lv);
}
__device__ __forceinline__ void split1h(float x, f16& h, f16& l){
    __half hv = __float2half_rn(x);
    h = hv;
    l = __float2half_rn(x - __half2float(hv));
}
__device__ __forceinline__ void ldm_x4(uint32_t* r, uint32_t addr){
    asm volatile("ldmatrix.sync.aligned.m8n8.x4.shared.b16 {%0,%1,%2,%3}, [%4];"
        : "=r"(r[0]),"=r"(r[1]),"=r"(r[2]),"=r"(r[3]) : "r"(addr));
}
__device__ __forceinline__ void ldm_x4t(uint32_t* r, uint32_t addr){
    asm volatile("ldmatrix.sync.aligned.m8n8.x4.trans.shared.b16 {%0,%1,%2,%3}, [%4];"
        : "=r"(r[0]),"=r"(r[1]),"=r"(r[2]),"=r"(r[3]) : "r"(addr));
}
__device__ __forceinline__ void mma_f16(float* c, const uint32_t* a, const uint32_t* b){
    asm volatile("mma.sync.aligned.m16n8k16.row.col.f32.f16.f16.f32 "
        "{%0,%1,%2,%3}, {%4,%5,%6,%7}, {%8,%9}, {%0,%1,%2,%3};"
        : "+f"(c[0]), "+f"(c[1]), "+f"(c[2]), "+f"(c[3])
        : "r"(a[0]), "r"(a[1]), "r"(a[2]), "r"(a[3]), "r"(b[0]), "r"(b[1]));
}
__device__ __forceinline__ void cp16(uint32_t s, const void* g, int sz){
    asm volatile("cp.async.ca.shared.global [%0], [%1], 16, %2;"
        :: "r"(s), "l"(g), "r"(sz) : "memory");
}
__device__ __forceinline__ void cp_commit(){ asm volatile("cp.async.commit_group;" ::: "memory"); }
template<int N> __device__ __forceinline__ void cp_wait(){ asm volatile("cp.async.wait_group %0;" :: "n"(N) : "memory"); }

// ---------------- GEMM: C = A * op(B), fp16 split, 128x128 tile, BK=32, single-sync ----
// NPROD 3: Ah*Bh + Ah*Bl + Al*Bh (warps 4m x 2n)
// NPROD 2: Ah*Bh + Ah*Bl         (warps 2m x 4n; Al never loaded/copied)
// NPROD 1: Ah*Bh                 (warps 2m x 4n; Al, Bl never loaded/copied)
// EPI 0: fp32   EPI 1: f16 hi+lo   EPI 2: f16 hi only
#define A_PITCH_B 80
#define BN_PITCH_B 80
#define BK_PITCH_B 272
#define STAGE_BYTES 40960
#define SMEM_DYN (2*STAGE_BYTES)

template<bool TRANS_B, bool CSKIP, bool CKLIM, int EPI, int NPROD>
__global__ void __launch_bounds__(256,2) tgemm_kernel(
    const f16* __restrict__ Ah, const f16* __restrict__ Al,
    const f16* __restrict__ Bh, const f16* __restrict__ Bl,
    float* __restrict__ Cf, f16* __restrict__ Ch, f16* __restrict__ Cl,
    int M, int N, int K, int lda, int ldb, int ldc,
    int divA, long long sA1, long long sA2,
    int divB, long long sB1, long long sB2,
    int divC, long long sC1, long long sC2)
{
    constexpr int BM = 128, BN = 128, BK = 32;
    constexpr int WMG = (NPROD == 3) ? 4 : 2;
    constexpr int WNG = 8 / WMG;
    constexpr int MT  = 8 / WMG;
    constexpr int NT  = 16 / WNG;
    constexpr int NPAIR = NT / 2;

    int by = blockIdx.y;
    if (CKLIM) by = gridDim.y - 1 - by;
    int m0 = by*BM, n0 = blockIdx.x*BN;
    if (CSKIP && n0 >= m0 + BM) return;
    int z = blockIdx.z;
    long long offA = (long long)(z/divA)*sA1 + (long long)(z%divA)*sA2;
    long long offB = (long long)(z/divB)*sB1 + (long long)(z%divB)*sB2;
    long long offC = (long long)(z/divC)*sC1 + (long long)(z%divC)*sC2;
    Ah += offA; Al += offA;
    Bh += offB; Bl += offB;
    if (EPI == 0) Cf += offC; else { Ch += offC; if (EPI == 1) Cl += offC; }
    int kEnd = CKLIM ? min(K, m0 + BM) : K;
    int nk = kEnd / BK;

    extern __shared__ __align__(128) char dyn_smem[];
    uint32_t sbase = smem_u32(dyn_smem);
    const uint32_t B_HI_OFF = (NPROD == 3) ? 20480u : 10240u;
    const uint32_t BLO_D = TRANS_B ? 10240u : 8704u;

    int tid  = threadIdx.x;
    int lane = tid & 31, wid = tid >> 5;
    int wm = wid % WMG, wn = wid / WMG;
    int mwarp = m0 + wm*(16*MT);
    int nwarp = n0 + wn*(8*NT);
    bool diag = CSKIP && (n0 == m0);

    int rowA = tid >> 1, segA = tid & 1;
    int rowB = tid >> 3, segB = tid & 7;

    auto copy_chunk = [&](int k0, uint32_t st){
        {
            const f16* g = Ah + (size_t)(m0+rowA)*lda + k0 + segA*16;
            uint32_t sd = st + (uint32_t)(rowA*A_PITCH_B + segA*32);
            cp16(sd, g, 16); cp16(sd+16, g+8, 16);
            if (NPROD == 3) {
                g = Al + (size_t)(m0+rowA)*lda + k0 + segA*16;
                sd += 10240;
                cp16(sd, g, 16); cp16(sd+16, g+8, 16);
            }
        }
        if (TRANS_B) {
            int ok = (n0+rowA) < N ? 16 : 0;
            size_t go = ok ? ((size_t)(n0+rowA)*ldb + k0 + segA*16) : 0;
            const f16* g = Bh + go;
            uint32_t sd = st + B_HI_OFF + (uint32_t)(rowA*BN_PITCH_B + segA*32);
            cp16(sd, g, ok); cp16(sd+16, g+8, ok);
            if (NPROD >= 2) {
                g = Bl + go;
                sd += BLO_D;
                cp16(sd, g, ok); cp16(sd+16, g+8, ok);
            }
        } else {
            const f16* g = Bh + (size_t)(k0+rowB)*ldb + n0 + segB*16;
            uint32_t sd = st + B_HI_OFF + (uint32_t)(rowB*BK_PITCH_B + segB*32);
            cp16(sd, g, 16); cp16(sd+16, g+8, 16);
            if (NPROD >= 2) {
                g = Bl + (size_t)(k0+rowB)*ldb + n0 + segB*16;
                sd += BLO_D;
                cp16(sd, g, 16); cp16(sd+16, g+8, 16);
            }
        }
    };

    float acc[MT][NT][4];
    #pragma unroll
    for (int i=0;i<MT;i++)
        #pragma unroll
        for (int j=0;j<NT;j++)
            #pragma unroll
            for (int q=0;q<4;q++) acc[i][j][q] = 0.f;

    uint32_t aOff   = (uint32_t)((wm*(16*MT) + (lane & 15))*A_PITCH_B + (lane >> 4)*16);
    uint32_t bOffT4 = (uint32_t)((wn*(8*NT) + (lane & 7) + ((lane >> 4)&1)*8)*BN_PITCH_B + ((lane >> 3)&1)*16);
    uint32_t bOffN4 = (uint32_t)((lane & 15)*BK_PITCH_B + wn*(8*NT)*2 + (lane >> 4)*16);

    copy_chunk(0, sbase);
    cp_commit();

    for (int kb = 0; kb < nk; kb++) {
        cp_wait<0>();
        __syncthreads();
        if (kb + 1 < nk) {
            copy_chunk((kb+1)*BK, sbase + ((kb+1)&1)*STAGE_BYTES);
            cp_commit();
        }

        uint32_t st = sbase + (kb&1)*STAGE_BYTES;
        uint32_t sAh = st, sAl = st + 10240;
        uint32_t sBh = st + B_HI_OFF, sBl = sBh + BLO_D;

        #pragma unroll
        for (int ks = 0; ks < 2; ks++) {
            uint32_t ah[MT][4], al[MT][4];
            #pragma unroll
            for (int mt = 0; mt < MT; mt++) {
                ldm_x4(ah[mt], sAh + aOff + (uint32_t)(mt*16*A_PITCH_B + ks*32));
                if (NPROD == 3)
                    ldm_x4(al[mt], sAl + aOff + (uint32_t)(mt*16*A_PITCH_B + ks*32));
            }

            uint32_t bh[2][4], bl[2][4];
            if (TRANS_B) {
                ldm_x4 (bh[0], sBh + bOffT4 + (uint32_t)(ks*32));
                if (NPROD >= 2) ldm_x4 (bl[0], sBl + bOffT4 + (uint32_t)(ks*32));
            } else {
                ldm_x4t(bh[0], sBh + bOffN4 + (uint32_t)(ks*16*BK_PITCH_B));
                if (NPROD >= 2) ldm_x4t(bl[0], sBl + bOffN4 + (uint32_t)(ks*16*BK_PITCH_B));
            }
            #pragma unroll
            for (int p = 0; p < NPAIR; p++) {
                int cur = p & 1, nxt = cur ^ 1;
                if (p < NPAIR-1) {
                    if (TRANS_B) {
                        ldm_x4 (bh[nxt], sBh + bOffT4 + (uint32_t)((p+1)*16*BN_PITCH_B + ks*32));
                        if (NPROD >= 2) ldm_x4 (bl[nxt], sBl + bOffT4 + (uint32_t)((p+1)*16*BN_PITCH_B + ks*32));
                    } else {
                        ldm_x4t(bh[nxt], sBh + bOffN4 + (uint32_t)((p+1)*32 + ks*16*BK_PITCH_B));
                        if (NPROD >= 2) ldm_x4t(bl[nxt], sBl + bOffN4 + (uint32_t)((p+1)*32 + ks*16*BK_PITCH_B));
                    }
                }
                #pragma unroll
                for (int q = 0; q < 2; q++) {
                    int nt = p*2 + q;
                    if (diag && (nwarp + nt*8) > (mwarp + 16*MT - 1)) continue;  // warp-uniform
                    const uint32_t* BH = &bh[cur][q*2];
                    const uint32_t* BL = &bl[cur][q*2];
                    #pragma unroll
                    for (int mt = 0; mt < MT; mt++) mma_f16(acc[mt][nt], ah[mt], BH);
                    if (NPROD >= 2) {
                        #pragma unroll
                        for (int mt = 0; mt < MT; mt++) mma_f16(acc[mt][nt], ah[mt], BL);
                    }
                    if (NPROD == 3) {
                        #pragma unroll
                        for (int mt = 0; mt < MT; mt++) mma_f16(acc[mt][nt], al[mt], BH);
                    }
                }
            }
        }
    }

    // ---- epilogue
    int rlo = lane >> 2;
    int cpair = (lane & 3)*2;
    #pragma unroll
    for (int mt = 0; mt < MT; mt++) {
        #pragma unroll
        for (int nt = 0; nt < NT; nt++) {
            int c = nwarp + nt*8 + cpair;
            if (c < N) {
                size_t r0 = (size_t)(mwarp + mt*16 + rlo);
                if (EPI == 0) {
                    *reinterpret_cast<float2*>(Cf + r0*ldc + c)     = make_float2(acc[mt][nt][0], acc[mt][nt][1]);
                    *reinterpret_cast<float2*>(Cf + (r0+8)*ldc + c) = make_float2(acc[mt][nt][2], acc[mt][nt][3]);
                } else {
                    uint32_t h, l;
                    split2h(acc[mt][nt][0], acc[mt][nt][1], h, l);
                    *reinterpret_cast<uint32_t*>(Ch + r0*ldc + c) = h;
                    if (EPI == 1) *reinterpret_cast<uint32_t*>(Cl + r0*ldc + c) = l;
                    split2h(acc[mt][nt][2], acc[mt][nt][3], h, l);
                    *reinterpret_cast<uint32_t*>(Ch + (r0+8)*ldc + c) = h;
                    if (EPI == 1) *reinterpret_cast<uint32_t*>(Cl + (r0+8)*ldc + c) = l;
                }
            }
        }
    }
}

// ---------------- single fused fp32 -> fp16 hi/lo split over all 5 tensors ----------------
__global__ void __launch_bounds__(256) split_all_kernel(
    const float* __restrict__ x, const float* __restrict__ wq,
    const float* __restrict__ wa, const float* __restrict__ wb,
    const float* __restrict__ wo)
{
    const long long c0 = (long long)BS_*DIM_/2;
    const long long c1 = c0 + (long long)NQ_*DIM_/2;
    const long long c2 = c1 + (long long)DQK_*DIM_/2;
    const long long c3 = c2 + (long long)4096*KVR_/2;
    const long long c4 = c3 + (long long)DIM_*H_*VD_/2;
    long long i = (long long)blockIdx.x*blockDim.x + threadIdx.x;
    if (i >= c4) return;
    const float* src; uint32_t *dh, *dl; long long j;
    if (i < c0)      { j = i;      src = x;  dh = (uint32_t*)g_x_h;    dl = (uint32_t*)g_x_l; }
    else if (i < c1) { j = i - c0; src = wq; dh = (uint32_t*)g_wq_h;   dl = (uint32_t*)g_wq_l; }
    else if (i < c2) { j = i - c1; src = wa; dh = (uint32_t*)g_wkva_h; dl = (uint32_t*)g_wkva_l; }
    else if (i < c3) { j = i - c2; src = wb; dh = (uint32_t*)g_wkvb_h; dl = (uint32_t*)g_wkvb_l; }
    else             { j = i - c3; src = wo; dh = (uint32_t*)g_wo_h;   dl = (uint32_t*)g_wo_l; }
    float2 v = reinterpret_cast<const float2*>(src)[j];
    uint32_t hh, ll;
    split2h(v.x, v.y, hh, ll);
    dh[j] = hh; dl[j] = ll;
}

// ---------------- RoPE tables ----------------
__global__ void rope_init_kernel() {
    int idx = blockIdx.x*blockDim.x + threadIdx.x;
    if (idx >= S_*(ROPE_/2)) return;
    int t = idx / (ROPE_/2);
    int i = idx % (ROPE_/2);
    double freq = pow(10000.0, -(double)(2*i)/(double)ROPE_);
    double ang  = (double)t * freq;
    g_cos[idx] = (float)cos(ang);
    g_sin[idx] = (float)sin(ang);
}

// ---------------- rmsnorm(kv_lat) + RoPE(k_pe, q_pe) -> split fp16 ----------------
__global__ void __launch_bounds__(256) prep_kernel(const float* __restrict__ kv_norm_w) {
    int bs  = blockIdx.x;
    int s   = bs % S_;
    int tid = threadIdx.x;
    const f16* kvh = g_kvr_h + (size_t)bs*DQK_;
    const f16* kvl = g_kvr_l + (size_t)bs*DQK_;
    f16* kfh = g_kf_h + (size_t)bs*DQK_;
    f16* kfl = g_kf_l + (size_t)bs*DQK_;

    __shared__ float red[256];
    float ss = 0.f;
    for (int j = tid; j < KVR_; j += 256) {
        float v = __half2float(kvh[j]) + __half2float(kvl[j]);
        ss += v*v;
    }
    red[tid] = ss; __syncthreads();
    #pragma unroll
    for (int o = 128; o > 0; o >>= 1) {
        if (tid < o) red[tid] += red[tid+o];
        __syncthreads();
    }
    float inv = 1.f / sqrtf(red[0] / (float)KVR_ + 1e-6f);

    for (int j = tid; j < KVR_; j += 256) {
        float v = __half2float(kvh[j]) + __half2float(kvl[j]);
        split1h(v * inv * kv_norm_w[j], kfh[j], kfl[j]);
    }

    for (int i = tid; i < ROPE_/2; i += 256) {
        float x0 = __half2float(kvh[KVR_+2*i]) + __half2float(kvl[KVR_+2*i]);
        float x1 = __half2float(kvh[KVR_+2*i+1]) + __half2float(kvl[KVR_+2*i+1]);
        float c = g_cos[s*(ROPE_/2)+i], sn = g_sin[s*(ROPE_/2)+i];
        split1h(x0*c - x1*sn, kfh[KVR_+2*i],   kfl[KVR_+2*i]);
        split1h(x0*sn + x1*c, kfh[KVR_+2*i+1], kfl[KVR_+2*i+1]);
    }

    const f16* qrh = g_qraw_h + (size_t)bs*NQ_;
    const f16* qrl = g_qraw_l + (size_t)bs*NQ_;
    f16* qfh = g_qf_h + (size_t)bs*H_*DQK_;
    for (int idx = tid; idx < H_*(ROPE_/2); idx += 256) {
        int h = idx >> 5, i = idx & 31;
        int src = h*QKH_ + NOPE_ + 2*i;
        float x0 = __half2float(qrh[src])   + __half2float(qrl[src]);
        float x1 = __half2float(qrh[src+1]) + __half2float(qrl[src+1]);
        float c = g_cos[s*(ROPE_/2)+i], sn = g_sin[s*(ROPE_/2)+i];
        int dst = h*DQK_ + KVR_ + 2*i;
        qfh[dst]   = __float2half_rn(x0*c - x1*sn);
        qfh[dst+1] = __float2half_rn(x0*sn + x1*c);
    }
}

// ---------------- lean causal softmax: fp32 scores -> fp16 hi attn ----------------
__global__ void __launch_bounds__(256) softmax_kernel() {
    int s = blockIdx.x;
    int z = blockIdx.y;
    size_t roff = ((size_t)z*S_ + s)*S_;
    const float* row = g_scores + roff;
    int n = s + 1;
    int pad = ((s >> 7) + 1) << 7;
    int tid = threadIdx.x;
    int base = tid*8;
    bool act = base < pad;

    float v[8];
    if (act) {
        *reinterpret_cast<float4*>(v)   = *reinterpret_cast<const float4*>(row + base);
        *reinterpret_cast<float4*>(v+4) = *reinterpret_cast<const float4*>(row + base + 4);
    }

    __shared__ float red[8];
    float mx = -3.4e38f;
    if (act) {
        #pragma unroll
        for (int e = 0; e < 8; e++) if (base + e < n) mx = fmaxf(mx, v[e]);
    }
    #pragma unroll
    for (int o = 16; o > 0; o >>= 1) mx = fmaxf(mx, __shfl_xor_sync(0xFFFFFFFFu, mx, o));
    if ((tid & 31) == 0) red[tid >> 5] = mx;
    __syncthreads();
    if (tid < 32) {
        float m = (tid < 8) ? red[tid] : -3.4e38f;
        #pragma unroll
        for (int o = 4; o > 0; o >>= 1) m = fmaxf(m, __shfl_xor_sync(0xFFFFFFFFu, m, o));
        if (tid == 0) red[0] = m;
    }
    __syncthreads();
    mx = red[0];
    __syncthreads();

    float e8[8];
    float sum = 0.f;
    #pragma unroll
    for (int e = 0; e < 8; e++) {
        float w = (act && base + e < n) ? expf((v[e] - mx) * SCALE_F) : 0.f;
        e8[e] = w; sum += w;
    }
    #pragma unroll
    for (int o = 16; o > 0; o >>= 1) sum += __shfl_xor_sync(0xFFFFFFFFu, sum, o);
    if ((tid & 31) == 0) red[tid >> 5] = sum;
    __syncthreads();
    if (tid < 32) {
        float m = (tid < 8) ? red[tid] : 0.f;
        #pragma unroll
        for (int o = 4; o > 0; o >>= 1) m += __shfl_xor_sync(0xFFFFFFFFu, m, o);
        if (tid == 0) red[0] = m;
    }
    __syncthreads();
    float inv = 1.f / red[0];

    if (act) {
        uint32_t* ah = reinterpret_cast<uint32_t*>(g_attn_h + roff + base);
        #pragma unroll
        for (int p = 0; p < 4; p++) {
            __half2 hv = __floats2half2_rn(e8[2*p]*inv, e8[2*p+1]*inv);
            ah[p] = *reinterpret_cast<uint32_t*>(&hv);
        }
    }
}

// ---------------- launch ----------------
extern "C" void kernel_launch(void* const* d_in, const int* in_sizes, int n_in,
                              void* d_out, int out_size) {
    const float* x      = (const float*)d_in[0];
    const float* wq     = (const float*)d_in[1];
    const float* wkv_a  = (const float*)d_in[2];
    const float* wkv_b  = (const float*)d_in[3];
    const float* wo     = (const float*)d_in[4];
    const float* kvw    = (const float*)d_in[5];
    float* out = (float*)d_out;

    f16 *xh,*xl,*wqh,*wql,*wah,*wal,*wbh,*wbl,*woh,*wol;
    f16 *qrh,*qrl,*kvh,*kvl,*kfh,*kfl,*qfh,*ath,*olh,*ovh;
    float *scores;
    cudaGetSymbolAddress((void**)&xh,  g_x_h);   cudaGetSymbolAddress((void**)&xl,  g_x_l);
    cudaGetSymbolAddress((void**)&wqh, g_wq_h);  cudaGetSymbolAddress((void**)&wql, g_wq_l);
    cudaGetSymbolAddress((void**)&wah, g_wkva_h);cudaGetSymbolAddress((void**)&wal, g_wkva_l);
    cudaGetSymbolAddress((void**)&wbh, g_wkvb_h);cudaGetSymbolAddress((void**)&wbl, g_wkvb_l);
    cudaGetSymbolAddress((void**)&woh, g_wo_h);  cudaGetSymbolAddress((void**)&wol, g_wo_l);
    cudaGetSymbolAddress((void**)&qrh, g_qraw_h);cudaGetSymbolAddress((void**)&qrl, g_qraw_l);
    cudaGetSymbolAddress((void**)&kvh, g_kvr_h); cudaGetSymbolAddress((void**)&kvl, g_kvr_l);
    cudaGetSymbolAddress((void**)&kfh, g_kf_h);  cudaGetSymbolAddress((void**)&kfl, g_kf_l);
    cudaGetSymbolAddress((void**)&qfh, g_qf_h);
    cudaGetSymbolAddress((void**)&ath, g_attn_h);
    cudaGetSymbolAddress((void**)&olh, g_ol_h);
    cudaGetSymbolAddress((void**)&ovh, g_ov_h);
    cudaGetSymbolAddress((void**)&scores, g_scores);

    cudaFuncSetAttribute(tgemm_kernel<true,false,false,1,3>,  cudaFuncAttributeMaxDynamicSharedMemorySize, SMEM_DYN);
    cudaFuncSetAttribute(tgemm_kernel<true,false,false,1,2>,  cudaFuncAttributeMaxDynamicSharedMemorySize, SMEM_DYN);
    cudaFuncSetAttribute(tgemm_kernel<false,false,false,2,2>, cudaFuncAttributeMaxDynamicSharedMemorySize, SMEM_DYN);
    cudaFuncSetAttribute(tgemm_kernel<true,true,false,0,1>,   cudaFuncAttributeMaxDynamicSharedMemorySize, SMEM_DYN);
    cudaFuncSetAttribute(tgemm_kernel<false,false,true,2,1>,  cudaFuncAttributeMaxDynamicSharedMemorySize, SMEM_DYN);
    cudaFuncSetAttribute(tgemm_kernel<true,false,false,2,2>,  cudaFuncAttributeMaxDynamicSharedMemorySize, SMEM_DYN);
    cudaFuncSetAttribute(tgemm_kernel<true,false,false,0,2>,  cudaFuncAttributeMaxDynamicSharedMemorySize, SMEM_DYN);

    const long long tot_pairs = (long long)BS_*DIM_/2 + (long long)NQ_*DIM_/2
        + (long long)DQK_*DIM_/2 + (long long)4096*KVR_/2 + (long long)DIM_*H_*VD_/2;

    // 0) fused hi/lo split
    split_all_kernel<<<(int)((tot_pairs + 255)/256), 256>>>(x, wq, wkv_a, wkv_b, wo);

    // 1) RoPE tables
    rope_init_kernel<<<(S_*(ROPE_/2)+255)/256, 256>>>();

    // 2) kv_raw = x @ wkv_a^T  (3 products; feeds rmsnorm/k-cache)
    tgemm_kernel<true,false,false,1,3><<<dim3((DQK_+127)/128, BS_/128, 1), 256, SMEM_DYN>>>(
        xh, xl, wah, wal, nullptr, kvh, kvl,
        BS_, DQK_, DIM_, DIM_, DIM_, DQK_,
        1,0,0, 1,0,0, 1,0,0);

    // 3) q_raw = x @ wq^T  (2 products)  <-- ncu captures 0-based launch index 3
    tgemm_kernel<true,false,false,1,2><<<dim3(NQ_/128, BS_/128, 1), 256, SMEM_DYN>>>(
        xh, xl, wqh, wql, nullptr, qrh, qrl,
        BS_, NQ_, DIM_, DIM_, DIM_, NQ_,
        1,0,0, 1,0,0, 1,0,0);

    // 4) rmsnorm + rope
    prep_kernel<<<BS_, 256>>>(kvw);

    // 5) q_lat[h] = q_nope[:,h] @ wkv_b_h[h,:128,:]  (2 products, hi-only epilogue)
    tgemm_kernel<false,false,false,2,2><<<dim3(KVR_/128, BS_/128, H_), 256, SMEM_DYN>>>(
        qrh, nullptr, wbh, wbl, nullptr, qfh, nullptr,
        BS_, KVR_, NOPE_, NQ_, KVR_, H_*DQK_,
        1, QKH_, 0,
        1, (long long)(NOPE_+VD_)*KVR_, 0,
        1, DQK_, 0);

    // 6) scores = qfull @ kfull^T  (1 product hh, causal tile skip + diag warp skip)
    tgemm_kernel<true,true,false,0,1><<<dim3(S_/128, S_/128, B_*H_), 256, SMEM_DYN>>>(
        qfh, nullptr, kfh, nullptr, scores, nullptr, nullptr,
        S_, S_, DQK_, H_*DQK_, DQK_, S_,
        H_, (long long)S_*H_*DQK_, DQK_,
        H_, (long long)S_*DQK_, 0,
        1, (long long)S_*S_, 0);

    // 7) lean softmax -> attn fp16 hi only
    softmax_kernel<<<dim3(S_, B_*H_), 256>>>();

    // 8) out_lat = attn @ kv_cache  (1 product hh, causal K-limit, hi-only out)
    tgemm_kernel<false,false,true,2,1><<<dim3(KVR_/128, S_/128, B_*H_), 256, SMEM_DYN>>>(
        ath, nullptr, kfh, nullptr, nullptr, olh, nullptr,
        S_, KVR_, S_, S_, DQK_, H_*KVR_,
        1, (long long)S_*S_, 0,
        H_, (long long)S_*DQK_, 0,
        H_, (long long)S_*H_*KVR_, KVR_);

    // 9) outv[:,h] = out_lat[:,h,:] @ wkv_b_h[h,128:,:]^T  (2 products, hi-only out)
    tgemm_kernel<true,false,false,2,2><<<dim3(VD_/128, BS_/128, H_), 256, SMEM_DYN>>>(
        olh, nullptr, wbh + (size_t)NOPE_*KVR_, wbl + (size_t)NOPE_*KVR_, nullptr, ovh, nullptr,
        BS_, VD_, KVR_, H_*KVR_, KVR_, H_*VD_,
        1, KVR_, 0,
        1, (long long)(NOPE_+VD_)*KVR_, 0,
        1, VD_, 0);

    // 10) out = outv @ wo^T  (2 products)
    tgemm_kernel<true,false,false,0,2><<<dim3(DIM_/128, BS_/128, 1), 256, SMEM_DYN>>>(
        ovh, nullptr, woh, wol, out, nullptr, nullptr,
        BS_, DIM_, H_*VD_, H_*VD_, H_*VD_, DIM_,
        1,0,0, 1,0,0, 1,0,0);
}

// round 17
// speedup vs baseline: 2.0464x; 1.1423x over previous
#include <cuda_runtime.h>
#include <cuda_fp16.h>
#include <math.h>
#include <stdint.h>

// ---------------- problem constants ----------------
#define B_    2
#define S_    2048
#define DIM_  2048
#define H_    16
#define NOPE_ 128
#define ROPE_ 64
#define QKH_  192
#define KVR_  512
#define VD_   128
#define DQK_  576
#define BS_   (B_*S_)      // 4096
#define NQ_   (H_*QKH_)    // 3072

static const float SCALE_F = 0.07216878364870323f;   // 192^-0.5
typedef __half f16;

// ---------------- scratch ----------------
__device__ f16 g_x_h   [(size_t)BS_*DIM_];
__device__ f16 g_x_l   [(size_t)BS_*DIM_];
__device__ f16 g_wq_h  [(size_t)NQ_*DIM_];
__device__ f16 g_wq_l  [(size_t)NQ_*DIM_];
__device__ f16 g_wkva_h[(size_t)DQK_*DIM_];
__device__ f16 g_wkva_l[(size_t)DQK_*DIM_];
__device__ f16 g_wkvb_h[(size_t)4096*KVR_];
__device__ f16 g_wkvb_l[(size_t)4096*KVR_];
__device__ f16 g_wo_h  [(size_t)DIM_*H_*VD_];
__device__ f16 g_wo_l  [(size_t)DIM_*H_*VD_];
__device__ f16 g_qraw_h[(size_t)BS_*NQ_];
__device__ f16 g_qraw_l[(size_t)BS_*NQ_];
__device__ f16 g_kvr_h [(size_t)BS_*DQK_];
__device__ f16 g_kvr_l [(size_t)BS_*DQK_];
__device__ f16 g_kf_h  [(size_t)BS_*DQK_];
__device__ float g_scores[(size_t)B_*H_*S_*S_];
__device__ f16 g_attn_h[(size_t)B_*H_*S_*S_];
__device__ f16 g_qf_h  [(size_t)BS_*H_*DQK_];
__device__ f16 g_ol_h  [(size_t)BS_*H_*KVR_];
__device__ f16 g_ov_h  [(size_t)BS_*H_*VD_];
__device__ float g_cos [S_*(ROPE_/2)];
__device__ float g_sin [S_*(ROPE_/2)];

// ---------------- helpers ----------------
__device__ __forceinline__ uint32_t smem_u32(const void* p){
    uint32_t a;
    asm("{ .reg .u64 t; cvta.to.shared.u64 t, %1; cvt.u32.u64 %0, t; }" : "=r"(a) : "l"(p));
    return a;
}
__device__ __forceinline__ void split2h(float x, float y, uint32_t& h, uint32_t& l){
    __half2 hv = __floats2half2_rn(x, y);
    float2 hf = __half22float2(hv);
    __half2 lv = __floats2half2_rn(x - hf.x, y - hf.y);
    h = *reinterpret_cast<uint32_t*>(&hv);
    l = *reinterpret_cast<uint32_t*>(&lv);
}
__device__ __forceinline__ void ldm_x4(uint32_t* r, uint32_t addr){
    asm volatile("ldmatrix.sync.aligned.m8n8.x4.shared.b16 {%0,%1,%2,%3}, [%4];"
        : "=r"(r[0]),"=r"(r[1]),"=r"(r[2]),"=r"(r[3]) : "r"(addr));
}
__device__ __forceinline__ void ldm_x4t(uint32_t* r, uint32_t addr){
    asm volatile("ldmatrix.sync.aligned.m8n8.x4.trans.shared.b16 {%0,%1,%2,%3}, [%4];"
        : "=r"(r[0]),"=r"(r[1]),"=r"(r[2]),"=r"(r[3]) : "r"(addr));
}
__device__ __forceinline__ void mma_f16(float* c, const uint32_t* a, const uint32_t* b){
    asm volatile("mma.sync.aligned.m16n8k16.row.col.f32.f16.f16.f32 "
        "{%0,%1,%2,%3}, {%4,%5,%6,%7}, {%8,%9}, {%0,%1,%2,%3};"
        : "+f"(c[0]), "+f"(c[1]), "+f"(c[2]), "+f"(c[3])
        : "r"(a[0]), "r"(a[1]), "r"(a[2]), "r"(a[3]), "r"(b[0]), "r"(b[1]));
}
__device__ __forceinline__ void cp16(uint32_t s, const void* g, int sz){
    asm volatile("cp.async.ca.shared.global [%0], [%1], 16, %2;"
        :: "r"(s), "l"(g), "r"(sz) : "memory");
}
__device__ __forceinline__ void cp_commit(){ asm volatile("cp.async.commit_group;" ::: "memory"); }
template<int N> __device__ __forceinline__ void cp_wait(){ asm volatile("cp.async.wait_group %0;" :: "n"(N) : "memory"); }

// ---------------- GEMM: C = A * op(B), fp16 split, 128x128 tile, BK=32, single-sync ----
// NPROD 3: Ah*Bh + Ah*Bl + Al*Bh (warps 4m x 2n)
// NPROD 2: Ah*Bh + Ah*Bl         (warps 2m x 4n; Al never loaded/copied)
// NPROD 1: Ah*Bh                 (warps 2m x 4n; Al, Bl never loaded/copied)
// EPI 0: fp32   EPI 1: f16 hi+lo   EPI 2: f16 hi only
#define A_PITCH_B 80
#define BN_PITCH_B 80
#define BK_PITCH_B 272
#define STAGE_BYTES 40960
#define SMEM_DYN (2*STAGE_BYTES)

template<bool TRANS_B, bool CSKIP, bool CKLIM, int EPI, int NPROD>
__global__ void __launch_bounds__(256,2) tgemm_kernel(
    const f16* __restrict__ Ah, const f16* __restrict__ Al,
    const f16* __restrict__ Bh, const f16* __restrict__ Bl,
    float* __restrict__ Cf, f16* __restrict__ Ch, f16* __restrict__ Cl,
    int M, int N, int K, int lda, int ldb, int ldc,
    int divA, long long sA1, long long sA2,
    int divB, long long sB1, long long sB2,
    int divC, long long sC1, long long sC2)
{
    constexpr int BM = 128, BN = 128, BK = 32;
    constexpr int WMG = (NPROD == 3) ? 4 : 2;
    constexpr int WNG = 8 / WMG;
    constexpr int MT  = 8 / WMG;
    constexpr int NT  = 16 / WNG;
    constexpr int NPAIR = NT / 2;

    int by = blockIdx.y;
    if (CKLIM) by = gridDim.y - 1 - by;
    int m0 = by*BM, n0 = blockIdx.x*BN;
    if (CSKIP && n0 >= m0 + BM) return;
    int z = blockIdx.z;
    long long offA = (long long)(z/divA)*sA1 + (long long)(z%divA)*sA2;
    long long offB = (long long)(z/divB)*sB1 + (long long)(z%divB)*sB2;
    long long offC = (long long)(z/divC)*sC1 + (long long)(z%divC)*sC2;
    Ah += offA; Al += offA;
    Bh += offB; Bl += offB;
    if (EPI == 0) Cf += offC; else { Ch += offC; if (EPI == 1) Cl += offC; }
    int kEnd = CKLIM ? min(K, m0 + BM) : K;
    int nk = kEnd / BK;

    extern __shared__ __align__(128) char dyn_smem[];
    uint32_t sbase = smem_u32(dyn_smem);
    const uint32_t B_HI_OFF = (NPROD == 3) ? 20480u : 10240u;
    const uint32_t BLO_D = TRANS_B ? 10240u : 8704u;

    int tid  = threadIdx.x;
    int lane = tid & 31, wid = tid >> 5;
    int wm = wid % WMG, wn = wid / WMG;
    int mwarp = m0 + wm*(16*MT);
    int nwarp = n0 + wn*(8*NT);
    bool diag = CSKIP && (n0 == m0);

    int rowA = tid >> 1, segA = tid & 1;
    int rowB = tid >> 3, segB = tid & 7;

    auto copy_chunk = [&](int k0, uint32_t st){
        {
            const f16* g = Ah + (size_t)(m0+rowA)*lda + k0 + segA*16;
            uint32_t sd = st + (uint32_t)(rowA*A_PITCH_B + segA*32);
            cp16(sd, g, 16); cp16(sd+16, g+8, 16);
            if (NPROD == 3) {
                g = Al + (size_t)(m0+rowA)*lda + k0 + segA*16;
                sd += 10240;
                cp16(sd, g, 16); cp16(sd+16, g+8, 16);
            }
        }
        if (TRANS_B) {
            int ok = (n0+rowA) < N ? 16 : 0;
            size_t go = ok ? ((size_t)(n0+rowA)*ldb + k0 + segA*16) : 0;
            const f16* g = Bh + go;
            uint32_t sd = st + B_HI_OFF + (uint32_t)(rowA*BN_PITCH_B + segA*32);
            cp16(sd, g, ok); cp16(sd+16, g+8, ok);
            if (NPROD >= 2) {
                g = Bl + go;
                sd += BLO_D;
                cp16(sd, g, ok); cp16(sd+16, g+8, ok);
            }
        } else {
            const f16* g = Bh + (size_t)(k0+rowB)*ldb + n0 + segB*16;
            uint32_t sd = st + B_HI_OFF + (uint32_t)(rowB*BK_PITCH_B + segB*32);
            cp16(sd, g, 16); cp16(sd+16, g+8, 16);
            if (NPROD >= 2) {
                g = Bl + (size_t)(k0+rowB)*ldb + n0 + segB*16;
                sd += BLO_D;
                cp16(sd, g, 16); cp16(sd+16, g+8, 16);
            }
        }
    };

    float acc[MT][NT][4];
    #pragma unroll
    for (int i=0;i<MT;i++)
        #pragma unroll
        for (int j=0;j<NT;j++)
            #pragma unroll
            for (int q=0;q<4;q++) acc[i][j][q] = 0.f;

    uint32_t aOff   = (uint32_t)((wm*(16*MT) + (lane & 15))*A_PITCH_B + (lane >> 4)*16);
    uint32_t bOffT4 = (uint32_t)((wn*(8*NT) + (lane & 7) + ((lane >> 4)&1)*8)*BN_PITCH_B + ((lane >> 3)&1)*16);
    uint32_t bOffN4 = (uint32_t)((lane & 15)*BK_PITCH_B + wn*(8*NT)*2 + (lane >> 4)*16);

    copy_chunk(0, sbase);
    cp_commit();

    for (int kb = 0; kb < nk; kb++) {
        cp_wait<0>();
        __syncthreads();
        if (kb + 1 < nk) {
            copy_chunk((kb+1)*BK, sbase + ((kb+1)&1)*STAGE_BYTES);
            cp_commit();
        }

        uint32_t st = sbase + (kb&1)*STAGE_BYTES;
        uint32_t sAh = st, sAl = st + 10240;
        uint32_t sBh = st + B_HI_OFF, sBl = sBh + BLO_D;

        #pragma unroll
        for (int ks = 0; ks < 2; ks++) {
            uint32_t ah[MT][4], al[MT][4];
            #pragma unroll
            for (int mt = 0; mt < MT; mt++) {
                ldm_x4(ah[mt], sAh + aOff + (uint32_t)(mt*16*A_PITCH_B + ks*32));
                if (NPROD == 3)
                    ldm_x4(al[mt], sAl + aOff + (uint32_t)(mt*16*A_PITCH_B + ks*32));
            }

            uint32_t bh[2][4], bl[2][4];
            if (TRANS_B) {
                ldm_x4 (bh[0], sBh + bOffT4 + (uint32_t)(ks*32));
                if (NPROD >= 2) ldm_x4 (bl[0], sBl + bOffT4 + (uint32_t)(ks*32));
            } else {
                ldm_x4t(bh[0], sBh + bOffN4 + (uint32_t)(ks*16*BK_PITCH_B));
                if (NPROD >= 2) ldm_x4t(bl[0], sBl + bOffN4 + (uint32_t)(ks*16*BK_PITCH_B));
            }
            #pragma unroll
            for (int p = 0; p < NPAIR; p++) {
                int cur = p & 1, nxt = cur ^ 1;
                if (p < NPAIR-1) {
                    if (TRANS_B) {
                        ldm_x4 (bh[nxt], sBh + bOffT4 + (uint32_t)((p+1)*16*BN_PITCH_B + ks*32));
                        if (NPROD >= 2) ldm_x4 (bl[nxt], sBl + bOffT4 + (uint32_t)((p+1)*16*BN_PITCH_B + ks*32));
                    } else {
                        ldm_x4t(bh[nxt], sBh + bOffN4 + (uint32_t)((p+1)*32 + ks*16*BK_PITCH_B));
                        if (NPROD >= 2) ldm_x4t(bl[nxt], sBl + bOffN4 + (uint32_t)((p+1)*32 + ks*16*BK_PITCH_B));
                    }
                }
                #pragma unroll
                for (int q = 0; q < 2; q++) {
                    int nt = p*2 + q;
                    if (diag && (nwarp + nt*8) > (mwarp + 16*MT - 1)) continue;  // warp-uniform
                    const uint32_t* BH = &bh[cur][q*2];
                    const uint32_t* BL = &bl[cur][q*2];
                    #pragma unroll
                    for (int mt = 0; mt < MT; mt++) mma_f16(acc[mt][nt], ah[mt], BH);
                    if (NPROD >= 2) {
                        #pragma unroll
                        for (int mt = 0; mt < MT; mt++) mma_f16(acc[mt][nt], ah[mt], BL);
                    }
                    if (NPROD == 3) {
                        #pragma unroll
                        for (int mt = 0; mt < MT; mt++) mma_f16(acc[mt][nt], al[mt], BH);
                    }
                }
            }
        }
    }

    // ---- epilogue
    int rlo = lane >> 2;
    int cpair = (lane & 3)*2;
    #pragma unroll
    for (int mt = 0; mt < MT; mt++) {
        #pragma unroll
        for (int nt = 0; nt < NT; nt++) {
            int c = nwarp + nt*8 + cpair;
            if (c < N) {
                size_t r0 = (size_t)(mwarp + mt*16 + rlo);
                if (EPI == 0) {
                    *reinterpret_cast<float2*>(Cf + r0*ldc + c)     = make_float2(acc[mt][nt][0], acc[mt][nt][1]);
                    *reinterpret_cast<float2*>(Cf + (r0+8)*ldc + c) = make_float2(acc[mt][nt][2], acc[mt][nt][3]);
                } else {
                    uint32_t h, l;
                    split2h(acc[mt][nt][0], acc[mt][nt][1], h, l);
                    *reinterpret_cast<uint32_t*>(Ch + r0*ldc + c) = h;
                    if (EPI == 1) *reinterpret_cast<uint32_t*>(Cl + r0*ldc + c) = l;
                    split2h(acc[mt][nt][2], acc[mt][nt][3], h, l);
                    *reinterpret_cast<uint32_t*>(Ch + (r0+8)*ldc + c) = h;
                    if (EPI == 1) *reinterpret_cast<uint32_t*>(Cl + (r0+8)*ldc + c) = l;
                }
            }
        }
    }
}

// ---------------- single fused fp32 -> fp16 hi/lo split over all 5 tensors ----------------
__global__ void __launch_bounds__(256) split_all_kernel(
    const float* __restrict__ x, const float* __restrict__ wq,
    const float* __restrict__ wa, const float* __restrict__ wb,
    const float* __restrict__ wo)
{
    const long long c0 = (long long)BS_*DIM_/2;
    const long long c1 = c0 + (long long)NQ_*DIM_/2;
    const long long c2 = c1 + (long long)DQK_*DIM_/2;
    const long long c3 = c2 + (long long)4096*KVR_/2;
    const long long c4 = c3 + (long long)DIM_*H_*VD_/2;
    long long i = (long long)blockIdx.x*blockDim.x + threadIdx.x;
    if (i >= c4) return;
    const float* src; uint32_t *dh, *dl; long long j;
    if (i < c0)      { j = i;      src = x;  dh = (uint32_t*)g_x_h;    dl = (uint32_t*)g_x_l; }
    else if (i < c1) { j = i - c0; src = wq; dh = (uint32_t*)g_wq_h;   dl = (uint32_t*)g_wq_l; }
    else if (i < c2) { j = i - c1; src = wa; dh = (uint32_t*)g_wkva_h; dl = (uint32_t*)g_wkva_l; }
    else if (i < c3) { j = i - c2; src = wb; dh = (uint32_t*)g_wkvb_h; dl = (uint32_t*)g_wkvb_l; }
    else             { j = i - c3; src = wo; dh = (uint32_t*)g_wo_h;   dl = (uint32_t*)g_wo_l; }
    float2 v = reinterpret_cast<const float2*>(src)[j];
    uint32_t hh, ll;
    split2h(v.x, v.y, hh, ll);
    dh[j] = hh; dl[j] = ll;
}

// ---------------- RoPE tables ----------------
__global__ void rope_init_kernel() {
    int idx = blockIdx.x*blockDim.x + threadIdx.x;
    if (idx >= S_*(ROPE_/2)) return;
    int t = idx / (ROPE_/2);
    int i = idx % (ROPE_/2);
    double freq = pow(10000.0, -(double)(2*i)/(double)ROPE_);
    double ang  = (double)t * freq;
    g_cos[idx] = (float)cos(ang);
    g_sin[idx] = (float)sin(ang);
}

// ---------------- rmsnorm(kv_lat) + RoPE(k_pe, q_pe) -> fp16 hi (kfl is dead) ----------------
__global__ void __launch_bounds__(256) prep_kernel(const float* __restrict__ kv_norm_w) {
    int bs  = blockIdx.x;
    int s   = bs % S_;
    int tid = threadIdx.x;
    const f16* kvh = g_kvr_h + (size_t)bs*DQK_;
    const f16* kvl = g_kvr_l + (size_t)bs*DQK_;
    f16* kfh = g_kf_h + (size_t)bs*DQK_;

    __shared__ float red[256];
    float ss = 0.f;
    for (int j = tid; j < KVR_; j += 256) {
        float v = __half2float(kvh[j]) + __half2float(kvl[j]);
        ss += v*v;
    }
    red[tid] = ss; __syncthreads();
    #pragma unroll
    for (int o = 128; o > 0; o >>= 1) {
        if (tid < o) red[tid] += red[tid+o];
        __syncthreads();
    }
    float inv = 1.f / sqrtf(red[0] / (float)KVR_ + 1e-6f);

    for (int j = tid; j < KVR_; j += 256) {
        float v = __half2float(kvh[j]) + __half2float(kvl[j]);
        kfh[j] = __float2half_rn(v * inv * kv_norm_w[j]);
    }

    for (int i = tid; i < ROPE_/2; i += 256) {
        float x0 = __half2float(kvh[KVR_+2*i]) + __half2float(kvl[KVR_+2*i]);
        float x1 = __half2float(kvh[KVR_+2*i+1]) + __half2float(kvl[KVR_+2*i+1]);
        float c = g_cos[s*(ROPE_/2)+i], sn = g_sin[s*(ROPE_/2)+i];
        kfh[KVR_+2*i]   = __float2half_rn(x0*c  - x1*sn);
        kfh[KVR_+2*i+1] = __float2half_rn(x0*sn + x1*c);
    }

    const f16* qrh = g_qraw_h + (size_t)bs*NQ_;
    const f16* qrl = g_qraw_l + (size_t)bs*NQ_;
    f16* qfh = g_qf_h + (size_t)bs*H_*DQK_;
    for (int idx = tid; idx < H_*(ROPE_/2); idx += 256) {
        int h = idx >> 5, i = idx & 31;
        int src = h*QKH_ + NOPE_ + 2*i;
        float x0 = __half2float(qrh[src])   + __half2float(qrl[src]);
        float x1 = __half2float(qrh[src+1]) + __half2float(qrl[src+1]);
        float c = g_cos[s*(ROPE_/2)+i], sn = g_sin[s*(ROPE_/2)+i];
        int dst = h*DQK_ + KVR_ + 2*i;
        qfh[dst]   = __float2half_rn(x0*c - x1*sn);
        qfh[dst+1] = __float2half_rn(x0*sn + x1*c);
    }
}

// ---------------- lean causal softmax: fp32 scores -> fp16 hi attn ----------------
__global__ void __launch_bounds__(256) softmax_kernel() {
    int s = blockIdx.x;
    int z = blockIdx.y;
    size_t roff = ((size_t)z*S_ + s)*S_;
    const float* row = g_scores + roff;
    int n = s + 1;
    int pad = ((s >> 7) + 1) << 7;
    int tid = threadIdx.x;
    int base = tid*8;
    bool act = base < pad;

    float v[8];
    if (act) {
        *reinterpret_cast<float4*>(v)   = *reinterpret_cast<const float4*>(row + base);
        *reinterpret_cast<float4*>(v+4) = *reinterpret_cast<const float4*>(row + base + 4);
    }

    __shared__ float red[8];
    float mx = -3.4e38f;
    if (act) {
        #pragma unroll
        for (int e = 0; e < 8; e++) if (base + e < n) mx = fmaxf(mx, v[e]);
    }
    #pragma unroll
    for (int o = 16; o > 0; o >>= 1) mx = fmaxf(mx, __shfl_xor_sync(0xFFFFFFFFu, mx, o));
    if ((tid & 31) == 0) red[tid >> 5] = mx;
    __syncthreads();
    if (tid < 32) {
        float m = (tid < 8) ? red[tid] : -3.4e38f;
        #pragma unroll
        for (int o = 4; o > 0; o >>= 1) m = fmaxf(m, __shfl_xor_sync(0xFFFFFFFFu, m, o));
        if (tid == 0) red[0] = m;
    }
    __syncthreads();
    mx = red[0];
    __syncthreads();

    float e8[8];
    float sum = 0.f;
    #pragma unroll
    for (int e = 0; e < 8; e++) {
        float w = (act && base + e < n) ? expf((v[e] - mx) * SCALE_F) : 0.f;
        e8[e] = w; sum += w;
    }
    #pragma unroll
    for (int o = 16; o > 0; o >>= 1) sum += __shfl_xor_sync(0xFFFFFFFFu, sum, o);
    if ((tid & 31) == 0) red[tid >> 5] = sum;
    __syncthreads();
    if (tid < 32) {
        float m = (tid < 8) ? red[tid] : 0.f;
        #pragma unroll
        for (int o = 4; o > 0; o >>= 1) m += __shfl_xor_sync(0xFFFFFFFFu, m, o);
        if (tid == 0) red[0] = m;
    }
    __syncthreads();
    float inv = 1.f / red[0];

    if (act) {
        uint32_t* ah = reinterpret_cast<uint32_t*>(g_attn_h + roff + base);
        #pragma unroll
        for (int p = 0; p < 4; p++) {
            __half2 hv = __floats2half2_rn(e8[2*p]*inv, e8[2*p+1]*inv);
            ah[p] = *reinterpret_cast<uint32_t*>(&hv);
        }
    }
}

// ---------------- launch ----------------
extern "C" void kernel_launch(void* const* d_in, const int* in_sizes, int n_in,
                              void* d_out, int out_size) {
    const float* x      = (const float*)d_in[0];
    const float* wq     = (const float*)d_in[1];
    const float* wkv_a  = (const float*)d_in[2];
    const float* wkv_b  = (const float*)d_in[3];
    const float* wo     = (const float*)d_in[4];
    const float* kvw    = (const float*)d_in[5];
    float* out = (float*)d_out;

    f16 *xh,*xl,*wqh,*wql,*wah,*wal,*wbh,*wbl,*woh,*wol;
    f16 *qrh,*qrl,*kvh,*kvl,*kfh,*qfh,*ath,*olh,*ovh;
    float *scores;
    cudaGetSymbolAddress((void**)&xh,  g_x_h);   cudaGetSymbolAddress((void**)&xl,  g_x_l);
    cudaGetSymbolAddress((void**)&wqh, g_wq_h);  cudaGetSymbolAddress((void**)&wql, g_wq_l);
    cudaGetSymbolAddress((void**)&wah, g_wkva_h);cudaGetSymbolAddress((void**)&wal, g_wkva_l);
    cudaGetSymbolAddress((void**)&wbh, g_wkvb_h);cudaGetSymbolAddress((void**)&wbl, g_wkvb_l);
    cudaGetSymbolAddress((void**)&woh, g_wo_h);  cudaGetSymbolAddress((void**)&wol, g_wo_l);
    cudaGetSymbolAddress((void**)&qrh, g_qraw_h);cudaGetSymbolAddress((void**)&qrl, g_qraw_l);
    cudaGetSymbolAddress((void**)&kvh, g_kvr_h); cudaGetSymbolAddress((void**)&kvl, g_kvr_l);
    cudaGetSymbolAddress((void**)&kfh, g_kf_h);
    cudaGetSymbolAddress((void**)&qfh, g_qf_h);
    cudaGetSymbolAddress((void**)&ath, g_attn_h);
    cudaGetSymbolAddress((void**)&olh, g_ol_h);
    cudaGetSymbolAddress((void**)&ovh, g_ov_h);
    cudaGetSymbolAddress((void**)&scores, g_scores);

    cudaFuncSetAttribute(tgemm_kernel<true,false,false,1,2>,  cudaFuncAttributeMaxDynamicSharedMemorySize, SMEM_DYN);
    cudaFuncSetAttribute(tgemm_kernel<true,false,false,1,1>,  cudaFuncAttributeMaxDynamicSharedMemorySize, SMEM_DYN);
    cudaFuncSetAttribute(tgemm_kernel<false,false,false,2,2>, cudaFuncAttributeMaxDynamicSharedMemorySize, SMEM_DYN);
    cudaFuncSetAttribute(tgemm_kernel<true,true,false,0,1>,   cudaFuncAttributeMaxDynamicSharedMemorySize, SMEM_DYN);
    cudaFuncSetAttribute(tgemm_kernel<false,false,true,2,1>,  cudaFuncAttributeMaxDynamicSharedMemorySize, SMEM_DYN);
    cudaFuncSetAttribute(tgemm_kernel<true,false,false,2,2>,  cudaFuncAttributeMaxDynamicSharedMemorySize, SMEM_DYN);
    cudaFuncSetAttribute(tgemm_kernel<true,false,false,0,1>,  cudaFuncAttributeMaxDynamicSharedMemorySize, SMEM_DYN);

    const long long tot_pairs = (long long)BS_*DIM_/2 + (long long)NQ_*DIM_/2
        + (long long)DQK_*DIM_/2 + (long long)4096*KVR_/2 + (long long)DIM_*H_*VD_/2;

    // 0) fused hi/lo split
    split_all_kernel<<<(int)((tot_pairs + 255)/256), 256>>>(x, wq, wkv_a, wkv_b, wo);

    // 1) RoPE tables
    rope_init_kernel<<<(S_*(ROPE_/2)+255)/256, 256>>>();

    // 2) kv_raw = x @ wkv_a^T  (2 products, hi+lo out; feeds rmsnorm)
    tgemm_kernel<true,false,false,1,2><<<dim3((DQK_+127)/128, BS_/128, 1), 256, SMEM_DYN>>>(
        xh, nullptr, wah, wal, nullptr, kvh, kvl,
        BS_, DQK_, DIM_, DIM_, DIM_, DQK_,
        1,0,0, 1,0,0, 1,0,0);

    // 3) q_raw = x @ wq^T  (1 product hh, hi+lo out)  <-- ncu index 3
    tgemm_kernel<true,false,false,1,1><<<dim3(NQ_/128, BS_/128, 1), 256, SMEM_DYN>>>(
        xh, nullptr, wqh, nullptr, nullptr, qrh, qrl,
        BS_, NQ_, DIM_, DIM_, DIM_, NQ_,
        1,0,0, 1,0,0, 1,0,0);

    // 4) rmsnorm + rope (kfl dead -> hi only)
    prep_kernel<<<BS_, 256>>>(kvw);

    // 5) q_lat[h] = q_nope[:,h] @ wkv_b_h[h,:128,:]  (2 products, hi-only epilogue)
    tgemm_kernel<false,false,false,2,2><<<dim3(KVR_/128, BS_/128, H_), 256, SMEM_DYN>>>(
        qrh, nullptr, wbh, wbl, nullptr, qfh, nullptr,
        BS_, KVR_, NOPE_, NQ_, KVR_, H_*DQK_,
        1, QKH_, 0,
        1, (long long)(NOPE_+VD_)*KVR_, 0,
        1, DQK_, 0);

    // 6) scores = qfull @ kfull^T  (1 product hh, causal tile skip + diag warp skip)
    tgemm_kernel<true,true,false,0,1><<<dim3(S_/128, S_/128, B_*H_), 256, SMEM_DYN>>>(
        qfh, nullptr, kfh, nullptr, scores, nullptr, nullptr,
        S_, S_, DQK_, H_*DQK_, DQK_, S_,
        H_, (long long)S_*H_*DQK_, DQK_,
        H_, (long long)S_*DQK_, 0,
        1, (long long)S_*S_, 0);

    // 7) lean softmax -> attn fp16 hi only
    softmax_kernel<<<dim3(S_, B_*H_), 256>>>();

    // 8) out_lat = attn @ kv_cache  (1 product hh, causal K-limit, hi-only out)
    tgemm_kernel<false,false,true,2,1><<<dim3(KVR_/128, S_/128, B_*H_), 256, SMEM_DYN>>>(
        ath, nullptr, kfh, nullptr, nullptr, olh, nullptr,
        S_, KVR_, S_, S_, DQK_, H_*KVR_,
        1, (long long)S_*S_, 0,
        H_, (long long)S_*DQK_, 0,
        H_, (long long)S_*H_*KVR_, KVR_);

    // 9) outv[:,h] = out_lat[:,h,:] @ wkv_b_h[h,128:,:]^T  (2 products, hi-only out)
    tgemm_kernel<true,false,false,2,2><<<dim3(VD_/128, BS_/128, H_), 256, SMEM_DYN>>>(
        olh, nullptr, wbh + (size_t)NOPE_*KVR_, wbl + (size_t)NOPE_*KVR_, nullptr, ovh, nullptr,
        BS_, VD_, KVR_, H_*KVR_, KVR_, H_*VD_,
        1, KVR_, 0,
        1, (long long)(NOPE_+VD_)*KVR_, 0,
        1, VD_, 0);

    // 10) out = outv @ wo^T  (1 product hh)
    tgemm_kernel<true,false,false,0,1><<<dim3(DIM_/128, BS_/128, 1), 256, SMEM_DYN>>>(
        ovh, nullptr, woh, nullptr, out, nullptr, nullptr,
        BS_, DIM_, H_*VD_, H_*VD_, H_*VD_, DIM_,
        1,0,0, 1,0,0, 1,0,0);
}